// round 15
// baseline (speedup 1.0000x reference)
#include <cuda_runtime.h>
#include <cuda_bf16.h>
#include <math.h>
#include <stdint.h>

#define BB 16
#define PP 1024
#define KNN 20
#define GB 8            // batches per group (2 groups)

// ---------------- scratch ----------------
__device__ float g_h0[BB * PP * 128];
__device__ __nv_bfloat16 g_h0h[BB * PP * 128];
__device__ __nv_bfloat16 g_h0l[BB * PP * 128];
__device__ __nv_bfloat16 g_xch[BB * PP * 512];
__device__ __nv_bfloat16 g_xcl[BB * PP * 512];
__device__ float g_uw[BB * PP * 512];              // group g owns [g*GB*PP*512, ...)
__device__ float g_pd[BB * PP * PP];
__device__ int   g_knn[BB * PP * KNN];
__device__ float g_sq[BB * PP];
__device__ float g_pmax[BB * 8 * 512];
__device__ float g_psum[BB * 8 * 512];
__device__ __nv_bfloat16 g_w1h[128 * 128], g_w1l[128 * 128];
__device__ __nv_bfloat16 g_w2h[128 * 64],  g_w2l[128 * 64];
__device__ __nv_bfloat16 g_w3h[256 * 64],  g_w3l[256 * 64];
__device__ __nv_bfloat16 g_w4h[512 * 128], g_w4l[512 * 128];
__device__ __nv_bfloat16 g_w5h[512 * 512], g_w5l[512 * 512];

__device__ __forceinline__ void bsplit(float x, __nv_bfloat16& hi, __nv_bfloat16& lo) {
    hi = __float2bfloat16(x);
    lo = __float2bfloat16(x - __bfloat162float(hi));
}

__device__ __forceinline__ uint32_t smem_u32(const void* p) {
    uint32_t a;
    asm("{ .reg .u64 t; cvta.to.shared.u64 t, %1; cvt.u32.u64 %0, t; }" : "=r"(a) : "l"(p));
    return a;
}

__device__ __forceinline__ void cp_async16(uint32_t dst, const void* src) {
    asm volatile("cp.async.ca.shared.global [%0], [%1], 16;"
                 :: "r"(dst), "l"(__cvta_generic_to_global(src)));
}
#define CP_COMMIT() asm volatile("cp.async.commit_group;")

__device__ __forceinline__ void mma16816(float* c, const uint32_t* a, const uint32_t* b) {
    asm volatile(
        "mma.sync.aligned.m16n8k16.row.col.f32.bf16.bf16.f32 "
        "{%0,%1,%2,%3}, {%4,%5,%6,%7}, {%8,%9}, {%0,%1,%2,%3};"
        : "+f"(c[0]), "+f"(c[1]), "+f"(c[2]), "+f"(c[3])
        : "r"(a[0]), "r"(a[1]), "r"(a[2]), "r"(a[3]), "r"(b[0]), "r"(b[1]));
}

__device__ __forceinline__ void ldsm4(uint32_t addr, uint32_t* r) {
    asm volatile("ldmatrix.sync.aligned.m8n8.x4.shared.b16 {%0,%1,%2,%3}, [%4];"
                 : "=r"(r[0]), "=r"(r[1]), "=r"(r[2]), "=r"(r[3]) : "r"(addr));
}

// ---------------- gather ----------------
__global__ void gather_kernel(const float* __restrict__ feats, const int* __restrict__ clusters) {
    int t = blockIdx.x * blockDim.x + threadIdx.x;
    if (t >= BB * PP * 32) return;
    int c4 = t & 31, bp = t >> 5;
    int src = clusters[bp];
    float4 v = reinterpret_cast<const float4*>(feats)[(size_t)src * 32 + c4];
    reinterpret_cast<float4*>(g_h0)[(size_t)bp * 32 + c4] = v;
    size_t e = (size_t)bp * 128 + c4 * 4;
    bsplit(v.x, g_h0h[e + 0], g_h0l[e + 0]);
    bsplit(v.y, g_h0h[e + 1], g_h0l[e + 1]);
    bsplit(v.z, g_h0h[e + 2], g_h0l[e + 2]);
    bsplit(v.w, g_h0h[e + 3], g_h0l[e + 3]);
}

// ---------------- squared norms (stage 1) ----------------
__global__ void sq_kernel(const float* __restrict__ h, int lda, int C) {
    int warp = (blockIdx.x * blockDim.x + threadIdx.x) >> 5;
    int lane = threadIdx.x & 31;
    if (warp >= BB * PP) return;
    const float* row = h + (size_t)warp * lda;
    float s = 0.f;
    for (int c = lane; c < C; c += 32) { float v = row[c]; s += v * v; }
    #pragma unroll
    for (int o = 16; o; o >>= 1) s += __shfl_xor_sync(0xffffffffu, s, o);
    if (lane == 0) g_sq[warp] = s;
}

// ---------------- merged weight prep ----------------
__global__ void prep_kernel(const float* __restrict__ W1, const float* __restrict__ W2,
                            const float* __restrict__ W3, const float* __restrict__ W4,
                            const float* __restrict__ W5) {
    int t = blockIdx.x * blockDim.x + threadIdx.x;
    if (t < 8192) {
        int o = t / 128, c = t % 128;
        float wa = W1[(size_t)o * 256 + c], wb = W1[(size_t)o * 256 + 128 + c];
        bsplit(wa, g_w1h[o * 128 + c], g_w1l[o * 128 + c]);
        bsplit(wb - wa, g_w1h[(64 + o) * 128 + c], g_w1l[(64 + o) * 128 + c]);
        return;
    }
    t -= 8192;
    if (t < 4096) {
        int o = t / 64, c = t % 64;
        float wa = W2[(size_t)o * 128 + c], wb = W2[(size_t)o * 128 + 64 + c];
        bsplit(wa, g_w2h[o * 64 + c], g_w2l[o * 64 + c]);
        bsplit(wb - wa, g_w2h[(64 + o) * 64 + c], g_w2l[(64 + o) * 64 + c]);
        return;
    }
    t -= 4096;
    if (t < 8192) {
        int o = t / 64, c = t % 64;
        float wa = W3[(size_t)o * 128 + c], wb = W3[(size_t)o * 128 + 64 + c];
        bsplit(wa, g_w3h[o * 64 + c], g_w3l[o * 64 + c]);
        bsplit(wb - wa, g_w3h[(128 + o) * 64 + c], g_w3l[(128 + o) * 64 + c]);
        return;
    }
    t -= 8192;
    if (t < 32768) {
        int o = t / 128, c = t % 128;
        float wa = W4[(size_t)o * 256 + c], wb = W4[(size_t)o * 256 + 128 + c];
        bsplit(wa, g_w4h[o * 128 + c], g_w4l[o * 128 + c]);
        bsplit(wb - wa, g_w4h[(256 + o) * 128 + c], g_w4l[(256 + o) * 128 + c]);
        return;
    }
    t -= 32768;
    if (t < 262144) {
        bsplit(W5[t], g_w5h[t], g_w5l[t]);
    }
}

// ---------------- shared GEMM pieces ----------------
#define EPI_PLAIN 0
#define EPI_POOL  2

#define STRIDE_W 20
#define ROW_B (STRIDE_W * 4)
#define TILE_BYTES (128 * ROW_B)
#define GEMM_SMEM (2 * 4 * TILE_BYTES)

// ldmatrix-based mainloop compute for one s (16-k slice). btoff selects B tile base.
#define GEMM_COMPUTE_S(sAaddr, btoff) \
    { \
        uint32_t ah[2][4], al[2][4]; \
        _Pragma("unroll") \
        for (int mf = 0; mf < 2; mf++) { \
            uint32_t ar = warp_m * 32 + mf * 16 + aoff; \
            uint32_t aaddr = (sAaddr) + ar * ROW_B + s * 32 + achunk * 16; \
            ldsm4(aaddr, ah[mf]); \
            ldsm4(aaddr + TILE_BYTES, al[mf]); \
        } \
        _Pragma("unroll") \
        for (int p = 0; p < 4; p++) { \
            uint32_t nr = warp_n * 64 + (2 * p + bhalf) * 8 + brow; \
            uint32_t baddr = (sAaddr) + (btoff) + nr * ROW_B + s * 32 + bchunk * 16; \
            uint32_t bhp[4], blp[4]; \
            ldsm4(baddr, bhp); \
            ldsm4(baddr + TILE_BYTES, blp); \
            _Pragma("unroll") \
            for (int hf = 0; hf < 2; hf++) { \
                int nf = 2 * p + hf; \
                uint32_t bh2[2] = { bhp[hf * 2], bhp[hf * 2 + 1] }; \
                uint32_t bl2[2] = { blp[hf * 2], blp[hf * 2 + 1] }; \
                _Pragma("unroll") \
                for (int mf = 0; mf < 2; mf++) { \
                    mma16816(acc[mf][nf], ah[mf], bh2); \
                    mma16816(acc[mf][nf], al[mf], bh2); \
                    mma16816(acc[mf][nf], ah[mf], bl2); \
                } \
            } \
        } \
    }

template<int EPI>
__global__ void __launch_bounds__(256)
mmagemm(const __nv_bfloat16* __restrict__ Ahi, const __nv_bfloat16* __restrict__ Alo,
        int lda, long sA, int acoff,
        const __nv_bfloat16* __restrict__ Bhi, const __nv_bfloat16* __restrict__ Blo,
        int ldb, long sB, int bcoff,
        float* __restrict__ Cout, int ldc, long sC,
        int K,
        const float* __restrict__ bn_s, const float* __restrict__ bn_b,
        float* __restrict__ pmax, float* __restrict__ psum) {
    extern __shared__ char dsm[];
    uint32_t smem_base = smem_u32(dsm);
    int tid = threadIdx.x;
    int lane = tid & 31, wid = tid >> 5;
    int warp_m = wid & 3, warp_n = wid >> 2;
    int g = lane >> 2, tid4 = lane & 3;
    int aoff = (lane & 7) + ((lane >> 3) & 1) * 8;
    int achunk = lane >> 4;
    int bhalf = (lane >> 4) & 1;
    int bchunk = (lane >> 3) & 1;
    int brow = lane & 7;
    int b = blockIdx.z;
    Ahi += (size_t)b * sA; Alo += (size_t)b * sA;
    Bhi += (size_t)b * sB; Blo += (size_t)b * sB;
    Cout += (size_t)b * sC;

    size_t aRow = (size_t)blockIdx.y * 128;
    size_t bRow = (size_t)blockIdx.x * 128;
    int nKb = K >> 5;

    float acc[2][8][4];
    #pragma unroll
    for (int mf = 0; mf < 2; mf++)
        #pragma unroll
        for (int nf = 0; nf < 8; nf++)
            #pragma unroll
            for (int i = 0; i < 4; i++) acc[mf][nf][i] = 0.f;

    auto load_block = [&](int buf, int kb) {
        uint32_t sbuf = smem_base + buf * 4 * TILE_BYTES;
        #pragma unroll
        for (int it = 0; it < 8; it++) {
            int i = tid + it * 256;
            int tile = i >> 9;
            int rem = i & 511;
            int row = rem >> 2;
            int chunk = rem & 3;
            uint32_t dst = sbuf + tile * TILE_BYTES + row * ROW_B + chunk * 16;
            const __nv_bfloat16* src;
            if (tile == 0)      src = Ahi + (aRow + row) * lda + acoff + kb * 32 + chunk * 8;
            else if (tile == 1) src = Alo + (aRow + row) * lda + acoff + kb * 32 + chunk * 8;
            else if (tile == 2) src = Bhi + (bRow + row) * ldb + bcoff + kb * 32 + chunk * 8;
            else                src = Blo + (bRow + row) * ldb + bcoff + kb * 32 + chunk * 8;
            cp_async16(dst, src);
        }
        CP_COMMIT();
    };

    load_block(0, 0);
    int buf = 0;
    for (int kb = 0; kb < nKb; kb++) {
        bool pref = (kb + 1 < nKb);
        if (pref) load_block(buf ^ 1, kb + 1);
        if (pref) asm volatile("cp.async.wait_group 1;");
        else      asm volatile("cp.async.wait_group 0;");
        __syncthreads();

        uint32_t sAaddr = smem_base + buf * 4 * TILE_BYTES;
        #pragma unroll
        for (int s = 0; s < 2; s++) {
            GEMM_COMPUTE_S(sAaddr, 2 * TILE_BYTES)
        }
        __syncthreads();
        buf ^= 1;
    }

    if (EPI == EPI_POOL) {
        float tmax[16], tsum[16];
        #pragma unroll
        for (int j = 0; j < 16; j++) { tmax[j] = -INFINITY; tsum[j] = 0.f; }
        #pragma unroll
        for (int nf = 0; nf < 8; nf++) {
            int c = warp_n * 64 + nf * 8 + 2 * tid4;
            float2 cs = *reinterpret_cast<const float2*>(&bn_s[blockIdx.x * 128 + c]);
            float2 cb = *reinterpret_cast<const float2*>(&bn_b[blockIdx.x * 128 + c]);
            #pragma unroll
            for (int mf = 0; mf < 2; mf++) {
                float v0 = acc[mf][nf][0] * cs.x + cb.x; v0 = (v0 > 0.f) ? v0 : 0.2f * v0;
                float v1 = acc[mf][nf][1] * cs.y + cb.y; v1 = (v1 > 0.f) ? v1 : 0.2f * v1;
                float v2 = acc[mf][nf][2] * cs.x + cb.x; v2 = (v2 > 0.f) ? v2 : 0.2f * v2;
                float v3 = acc[mf][nf][3] * cs.y + cb.y; v3 = (v3 > 0.f) ? v3 : 0.2f * v3;
                tmax[nf * 2 + 0] = fmaxf(tmax[nf * 2 + 0], fmaxf(v0, v2));
                tmax[nf * 2 + 1] = fmaxf(tmax[nf * 2 + 1], fmaxf(v1, v3));
                tsum[nf * 2 + 0] += v0 + v2;
                tsum[nf * 2 + 1] += v1 + v3;
            }
        }
        #pragma unroll
        for (int off = 4; off <= 16; off <<= 1) {
            #pragma unroll
            for (int j = 0; j < 16; j++) {
                tmax[j] = fmaxf(tmax[j], __shfl_xor_sync(0xffffffffu, tmax[j], off));
                tsum[j] += __shfl_xor_sync(0xffffffffu, tsum[j], off);
            }
        }
        float* st = (float*)dsm;
        if (g == 0) {
            int base = ((warp_m * 2 + warp_n) * 4 + tid4) * 32;
            #pragma unroll
            for (int j = 0; j < 16; j++) { st[base + j] = tmax[j]; st[base + 16 + j] = tsum[j]; }
        }
        __syncthreads();
        if (warp_m == 0 && g == 0) {
            #pragma unroll
            for (int j = 0; j < 16; j++) {
                float m = -INFINITY, s = 0.f;
                #pragma unroll
                for (int wm = 0; wm < 4; wm++) {
                    int base = ((wm * 2 + warp_n) * 4 + tid4) * 32;
                    m = fmaxf(m, st[base + j]);
                    s += st[base + 16 + j];
                }
                int c = warp_n * 64 + (j >> 1) * 8 + 2 * tid4 + (j & 1);
                pmax[(size_t)blockIdx.y * 512 + blockIdx.x * 128 + c] = m;
                psum[(size_t)blockIdx.y * 512 + blockIdx.x * 128 + c] = s;
            }
        }
    } else {
        #pragma unroll
        for (int mf = 0; mf < 2; mf++) {
            size_t r0 = aRow + warp_m * 32 + mf * 16 + g;
            size_t r1 = r0 + 8;
            #pragma unroll
            for (int nf = 0; nf < 8; nf++) {
                size_t c = (size_t)blockIdx.x * 128 + warp_n * 64 + nf * 8 + 2 * tid4;
                *reinterpret_cast<float2*>(&Cout[r0 * ldc + c]) = make_float2(acc[mf][nf][0], acc[mf][nf][1]);
                *reinterpret_cast<float2*>(&Cout[r1 * ldc + c]) = make_float2(acc[mf][nf][2], acc[mf][nf][3]);
            }
        }
    }
}

// ---------------- symmetric pd GEMM (lower triangle, diag tile sharing, mirrored write) ----------------
__global__ void __launch_bounds__(256)
pdsym(const __nv_bfloat16* __restrict__ Ahi, const __nv_bfloat16* __restrict__ Alo,
      int lda, long sA, int acoff, int K, int bbase) {
    extern __shared__ char dsm[];
    uint32_t smem_base = smem_u32(dsm);
    int tid = threadIdx.x;
    int lane = tid & 31, wid = tid >> 5;
    int warp_m = wid & 3, warp_n = wid >> 2;
    int g = lane >> 2, tid4 = lane & 3;
    int aoff = (lane & 7) + ((lane >> 3) & 1) * 8;
    int achunk = lane >> 4;
    int bhalf = (lane >> 4) & 1;
    int bchunk = (lane >> 3) & 1;
    int brow = lane & 7;
    int b = bbase + blockIdx.z;
    const __nv_bfloat16* Hh = Ahi + (size_t)b * sA;
    const __nv_bfloat16* Hl = Alo + (size_t)b * sA;
    float* pd = g_pd + (size_t)b * PP * PP;
    const float* sqb = g_sq + (size_t)b * PP;

    int t36 = blockIdx.x, by = 0;
    while (t36 > by) { t36 -= by + 1; by++; }
    int bx = t36;
    bool diag = (bx == by);
    uint32_t btoff = diag ? 0u : (uint32_t)(2 * TILE_BYTES);
    int nchunks = diag ? 1024 : 2048;

    size_t aRow = (size_t)by * 128;
    size_t bRow = (size_t)bx * 128;
    int nKb = K >> 5;

    float acc[2][8][4];
    #pragma unroll
    for (int mf = 0; mf < 2; mf++)
        #pragma unroll
        for (int nf = 0; nf < 8; nf++)
            #pragma unroll
            for (int i = 0; i < 4; i++) acc[mf][nf][i] = 0.f;

    auto load_block = [&](int buf, int kb) {
        uint32_t sbuf = smem_base + buf * 4 * TILE_BYTES;
        #pragma unroll
        for (int it = 0; it < 8; it++) {
            int i = tid + it * 256;
            if (i >= nchunks) break;
            int tile = i >> 9;
            int rem = i & 511;
            int row = rem >> 2;
            int chunk = rem & 3;
            uint32_t dst = sbuf + tile * TILE_BYTES + row * ROW_B + chunk * 16;
            const __nv_bfloat16* src;
            if (tile == 0)      src = Hh + (aRow + row) * lda + acoff + kb * 32 + chunk * 8;
            else if (tile == 1) src = Hl + (aRow + row) * lda + acoff + kb * 32 + chunk * 8;
            else if (tile == 2) src = Hh + (bRow + row) * lda + acoff + kb * 32 + chunk * 8;
            else                src = Hl + (bRow + row) * lda + acoff + kb * 32 + chunk * 8;
            cp_async16(dst, src);
        }
        CP_COMMIT();
    };

    load_block(0, 0);
    int buf = 0;
    for (int kb = 0; kb < nKb; kb++) {
        bool pref = (kb + 1 < nKb);
        if (pref) load_block(buf ^ 1, kb + 1);
        if (pref) asm volatile("cp.async.wait_group 1;");
        else      asm volatile("cp.async.wait_group 0;");
        __syncthreads();

        uint32_t sAaddr = smem_base + buf * 4 * TILE_BYTES;
        #pragma unroll
        for (int s = 0; s < 2; s++) {
            GEMM_COMPUTE_S(sAaddr, btoff)
        }
        __syncthreads();
        buf ^= 1;
    }

    #pragma unroll
    for (int mf = 0; mf < 2; mf++) {
        size_t r0 = aRow + warp_m * 32 + mf * 16 + g;
        size_t r1 = r0 + 8;
        #pragma unroll
        for (int nf = 0; nf < 8; nf++) {
            size_t c = bRow + warp_n * 64 + nf * 8 + 2 * tid4;
            float2 cs = *reinterpret_cast<const float2*>(&sqb[c]);
            *reinterpret_cast<float2*>(&pd[r0 * PP + c]) =
                make_float2(2.f * acc[mf][nf][0] - cs.x, 2.f * acc[mf][nf][1] - cs.y);
            *reinterpret_cast<float2*>(&pd[r1 * PP + c]) =
                make_float2(2.f * acc[mf][nf][2] - cs.x, 2.f * acc[mf][nf][3] - cs.y);
        }
    }

    if (!diag) {
        float* st = (float*)dsm;
        #pragma unroll
        for (int mf = 0; mf < 2; mf++) {
            int rl0 = warp_m * 32 + mf * 16 + g;
            int rl1 = rl0 + 8;
            #pragma unroll
            for (int nf = 0; nf < 8; nf++) {
                int cl = warp_n * 64 + nf * 8 + 2 * tid4;
                st[rl0 * 129 + cl]     = 2.f * acc[mf][nf][0];
                st[rl0 * 129 + cl + 1] = 2.f * acc[mf][nf][1];
                st[rl1 * 129 + cl]     = 2.f * acc[mf][nf][2];
                st[rl1 * 129 + cl + 1] = 2.f * acc[mf][nf][3];
            }
        }
        __syncthreads();
        for (int i = tid; i < 128 * 32; i += 256) {
            int cl = i >> 5;
            int r  = (i & 31) * 4;
            float4 sv;
            sv.x = st[(r + 0) * 129 + cl];
            sv.y = st[(r + 1) * 129 + cl];
            sv.z = st[(r + 2) * 129 + cl];
            sv.w = st[(r + 3) * 129 + cl];
            float4 sq4 = *reinterpret_cast<const float4*>(&sqb[aRow + r]);
            float4 o = make_float4(sv.x - sq4.x, sv.y - sq4.y, sv.z - sq4.z, sv.w - sq4.w);
            *reinterpret_cast<float4*>(&pd[(bRow + cl) * PP + aRow + r]) = o;
        }
    }
}

// ---------------- top-20 per row: register-resident, float4 loads ----------------
// lane owns contiguous j = lane*32 + idx (idx 0..31); ascending-idx scan keeps
// lowest index on ties, warp argmax compares global indices -> same knn output.
__global__ void __launch_bounds__(256) topk_kernel(int rowbase) {
    int warp = threadIdx.x >> 5, lane = threadIdx.x & 31;
    int row = rowbase + blockIdx.x * 8 + warp;
    const float* __restrict__ prow = g_pd + (size_t)row * PP;
    const float4* __restrict__ p4 = reinterpret_cast<const float4*>(prow + lane * 32);

    float v[32];
    #pragma unroll
    for (int q = 0; q < 8; q++) {
        float4 t = __ldg(&p4[q]);
        v[q * 4 + 0] = t.x; v[q * 4 + 1] = t.y; v[q * 4 + 2] = t.z; v[q * 4 + 3] = t.w;
    }
    int jbase = lane * 32;

    float m1 = -INFINITY, m2 = -INFINITY;
    int i1 = PP, i2 = PP;
    #pragma unroll
    for (int idx = 0; idx < 32; idx++) {
        float x = v[idx];
        int j = jbase + idx;
        if (x > m1) { m2 = m1; i2 = i1; m1 = x; i1 = j; }
        else if (x > m2) { m2 = x; i2 = j; }
    }
    bool have2 = true;
    unsigned mask = 0;

    for (int k = 0; k < KNN; k++) {
        float best = m1; int bi = i1;
        #pragma unroll
        for (int o = 16; o; o >>= 1) {
            float ov = __shfl_xor_sync(0xffffffffu, best, o);
            int   oi = __shfl_xor_sync(0xffffffffu, bi, o);
            if (ov > best || (ov == best && oi < bi)) { best = ov; bi = oi; }
        }
        if (lane == 0) g_knn[row * KNN + k] = bi;
        if (i1 == bi) {
            mask |= 1u << (bi & 31);
            if (have2) { m1 = m2; i1 = i2; have2 = false; }
            else {
                m1 = -INFINITY; m2 = -INFINITY; i1 = PP; i2 = PP;
                #pragma unroll
                for (int idx = 0; idx < 32; idx++) {
                    if (!(mask & (1u << idx))) {
                        float x = v[idx];
                        int j = jbase + idx;
                        if (x > m1) { m2 = m1; i2 = i1; m1 = x; i1 = j; }
                        else if (x > m2) { m2 = x; i2 = j; }
                    }
                }
                have2 = true;
            }
        }
    }
}

// ---------------- aggregate + fused next-stage sq + bf16 split output ----------------
__global__ void __launch_bounds__(256) agg_kernel(
    const float* __restrict__ uw,
    const float* __restrict__ s, const float* __restrict__ bias,
    int O, int coloff, float* __restrict__ sqout, int bbase) {
    __shared__ int sidx[128];
    __shared__ float red[256];
    int tid = threadIdx.x;
    int G = 256 / O;
    int pi = tid / O;
    int o = tid - pi * O;
    int bl = blockIdx.y;
    int b = bbase + bl;
    int p = blockIdx.x * G + pi;
    size_t base = (size_t)b * PP + p;

    if (tid < G * KNN) {
        int gp = tid / KNN, kk = tid - gp * KNN;
        sidx[tid] = g_knn[((size_t)b * PP + blockIdx.x * G + gp) * KNN + kk];
    }
    __syncthreads();

    int twoO = 2 * O;
    const float* __restrict__ ub = uw + (size_t)bl * PP * twoO;
    float wv = __ldg(&ub[(size_t)p * twoO + O + o]);
    float sv = s[o], bv = bias[o];
    const int* idx = sidx + pi * KNN;
    float m = -INFINITY;
    #pragma unroll
    for (int k = 0; k < KNN; k++) {
        int nb = idx[k];
        float y = __ldg(&ub[(size_t)nb * twoO + o]) + wv;
        y = y * sv + bv;
        y = (y > 0.f) ? y : 0.2f * y;
        m = fmaxf(m, y);
    }
    bsplit(m, g_xch[base * 512 + coloff + o], g_xcl[base * 512 + coloff + o]);

    red[tid] = m * m;
    __syncthreads();
    for (int st = O >> 1; st > 0; st >>= 1) {
        if (o < st) red[tid] += red[tid + st];
        __syncthreads();
    }
    if (o == 0) sqout[base] = red[tid];
}

// ---------------- MLP head (with inline pool combine) ----------------
__global__ void head_kernel(const float* __restrict__ L1, const float* __restrict__ s6, const float* __restrict__ b6,
                            const float* __restrict__ L2, const float* __restrict__ bl2,
                            const float* __restrict__ s7, const float* __restrict__ b7,
                            const float* __restrict__ L3, const float* __restrict__ bl3,
                            float* __restrict__ out) {
    __shared__ float sf[1024];
    __shared__ float z1[512];
    __shared__ float z2[256];
    int b = blockIdx.x, t = threadIdx.x;
    {
        float mx = -INFINITY, sm = 0.f;
        #pragma unroll
        for (int c = 0; c < 8; c++) {
            mx = fmaxf(mx, g_pmax[(b * 8 + c) * 512 + t]);
            sm += g_psum[(b * 8 + c) * 512 + t];
        }
        sf[t] = mx;
        sf[t + 512] = sm * (1.0f / PP);
    }
    __syncthreads();
    {
        float a = 0.f;
        const float* r = L1 + (size_t)t * 1024;
        for (int j = 0; j < 1024; j++) a += sf[j] * r[j];
        a = a * s6[t] + b6[t];
        z1[t] = (a > 0.f) ? a : 0.2f * a;
    }
    __syncthreads();
    if (t < 256) {
        float a = 0.f;
        const float* r = L2 + (size_t)t * 512;
        for (int j = 0; j < 512; j++) a += z1[j] * r[j];
        a = (a + bl2[t]) * s7[t] + b7[t];
        a = (a > 0.f) ? a : 0.2f * a;
        z2[t] = a * L3[t];
    }
    __syncthreads();
    if (t < 128) z2[t] += z2[t + 128];
    __syncthreads();
    if (t < 64) z2[t] += z2[t + 64];
    __syncthreads();
    if (t < 32) {
        float v = z2[t] + z2[t + 32];
        #pragma unroll
        for (int o = 16; o; o >>= 1) v += __shfl_down_sync(0xffffffffu, v, o);
        if (t == 0) {
            float z = v + bl3[0];
            out[b] = 1.0f / (1.0f + expf(-z));
        }
    }
}

// ---------------- host orchestration ----------------
extern "C" void kernel_launch(void* const* d_in, const int* in_sizes, int n_in,
                              void* d_out, int out_size) {
    const int* clusters;
    const float* features;
    if (in_sizes[0] == BB * PP) {
        clusters = (const int*)d_in[0];
        features = (const float*)d_in[1];
    } else {
        features = (const float*)d_in[0];
        clusters = (const int*)d_in[1];
    }
    const float* W1  = (const float*)d_in[2];
    const float* s1p = (const float*)d_in[3];
    const float* b1  = (const float*)d_in[4];
    const float* W2  = (const float*)d_in[5];
    const float* s2  = (const float*)d_in[6];
    const float* b2  = (const float*)d_in[7];
    const float* W3  = (const float*)d_in[8];
    const float* s3  = (const float*)d_in[9];
    const float* b3  = (const float*)d_in[10];
    const float* W4  = (const float*)d_in[11];
    const float* s4  = (const float*)d_in[12];
    const float* b4  = (const float*)d_in[13];
    const float* W5  = (const float*)d_in[14];
    const float* s5  = (const float*)d_in[15];
    const float* b5  = (const float*)d_in[16];
    const float* L1  = (const float*)d_in[17];
    const float* s6  = (const float*)d_in[18];
    const float* b6  = (const float*)d_in[19];
    const float* L2  = (const float*)d_in[20];
    const float* bl2 = (const float*)d_in[21];
    const float* s7  = (const float*)d_in[22];
    const float* b7  = (const float*)d_in[23];
    const float* L3  = (const float*)d_in[24];
    const float* bl3 = (const float*)d_in[25];
    float* out = (float*)d_out;

    static cudaStream_t s1s = nullptr;
    static cudaEvent_t evRoot, evA, evP, evG1;
    if (!s1s) {
        cudaFuncSetAttribute(mmagemm<EPI_PLAIN>, cudaFuncAttributeMaxDynamicSharedMemorySize, GEMM_SMEM);
        cudaFuncSetAttribute(mmagemm<EPI_POOL>,  cudaFuncAttributeMaxDynamicSharedMemorySize, GEMM_SMEM);
        cudaFuncSetAttribute(pdsym,              cudaFuncAttributeMaxDynamicSharedMemorySize, GEMM_SMEM);
        cudaStreamCreateWithFlags(&s1s, cudaStreamNonBlocking);
        cudaEventCreateWithFlags(&evRoot, cudaEventDisableTiming);
        cudaEventCreateWithFlags(&evA, cudaEventDisableTiming);
        cudaEventCreateWithFlags(&evP, cudaEventDisableTiming);
        cudaEventCreateWithFlags(&evG1, cudaEventDisableTiming);
    }

    float *h0, *uw, *sq, *pmax, *psum;
    __nv_bfloat16 *h0h, *h0l, *xch, *xcl;
    __nv_bfloat16 *w1h, *w1l, *w2h, *w2l, *w3h, *w3l, *w4h, *w4l, *w5h, *w5l;
    cudaGetSymbolAddress((void**)&h0, g_h0);
    cudaGetSymbolAddress((void**)&uw, g_uw);
    cudaGetSymbolAddress((void**)&sq, g_sq);
    cudaGetSymbolAddress((void**)&pmax, g_pmax);
    cudaGetSymbolAddress((void**)&psum, g_psum);
    cudaGetSymbolAddress((void**)&h0h, g_h0h);
    cudaGetSymbolAddress((void**)&h0l, g_h0l);
    cudaGetSymbolAddress((void**)&xch, g_xch);
    cudaGetSymbolAddress((void**)&xcl, g_xcl);
    cudaGetSymbolAddress((void**)&w1h, g_w1h); cudaGetSymbolAddress((void**)&w1l, g_w1l);
    cudaGetSymbolAddress((void**)&w2h, g_w2h); cudaGetSymbolAddress((void**)&w2l, g_w2l);
    cudaGetSymbolAddress((void**)&w3h, g_w3h); cudaGetSymbolAddress((void**)&w3l, g_w3l);
    cudaGetSymbolAddress((void**)&w4h, g_w4h); cudaGetSymbolAddress((void**)&w4l, g_w4l);
    cudaGetSymbolAddress((void**)&w5h, g_w5h); cudaGetSymbolAddress((void**)&w5l, g_w5l);

    const __nv_bfloat16* hh[4] = { h0h, xch, xch, xch };
    const __nv_bfloat16* hl[4] = { h0l, xcl, xcl, xcl };
    int lda_s[4]   = { 128, 512, 512, 512 };
    int coff_s[4]  = { 0, 0, 64, 128 };
    int C_s[4]     = { 128, 64, 64, 128 };
    int O_s[4]     = { 64, 64, 128, 256 };
    const __nv_bfloat16* wh_s[4] = { w1h, w2h, w3h, w4h };
    const __nv_bfloat16* wl_s[4] = { w1l, w2l, w3l, w4l };
    const float* ss_s[4] = { s1p, s2, s3, s4 };
    const float* bb_s[4] = { b1, b2, b3, b4 };
    int ocoff_s[4] = { 0, 64, 128, 256 };

    // fork: prep on side stream
    cudaEventRecord(evRoot, 0);
    cudaStreamWaitEvent(s1s, evRoot, 0);
    prep_kernel<<<(8192 + 4096 + 8192 + 32768 + 262144 + 255) / 256, 256, 0, s1s>>>(W1, W2, W3, W4, W5);
    cudaEventRecord(evP, s1s);

    gather_kernel<<<(BB * PP * 32 + 255) / 256, 256>>>(features, clusters);
    sq_kernel<<<BB * PP / 8, 256>>>(h0, 128, 128);
    cudaEventRecord(evA, 0);

    cudaStreamWaitEvent(0, evP, 0);
    cudaStreamWaitEvent(s1s, evA, 0);

    cudaStream_t streams[2] = { 0, s1s };
    for (int grp = 0; grp < 2; grp++) {
        cudaStream_t st = streams[grp];
        int bbase = grp * GB;
        float* uwg = uw + (size_t)grp * GB * PP * 512;

        for (int s = 0; s < 4; s++) {
            long strideA = (long)PP * lda_s[s];
            int C = C_s[s], O = O_s[s];
            size_t hoff = (size_t)bbase * PP * lda_s[s];

            // critical-path producer first
            pdsym<<<dim3(36, 1, GB), 256, GEMM_SMEM, st>>>(
                hh[s], hl[s], lda_s[s], strideA, coff_s[s], C, bbase);

            // uw fills remaining SMs; consumed only by agg
            mmagemm<EPI_PLAIN><<<dim3((2 * O) / 128, (GB * PP) / 128, 1), 256, GEMM_SMEM, st>>>(
                hh[s] + hoff, hl[s] + hoff, lda_s[s], 0, coff_s[s],
                wh_s[s], wl_s[s], C, 0, 0,
                uwg, 2 * O, 0,
                C, nullptr, nullptr, nullptr, nullptr);

            topk_kernel<<<GB * PP / 8, 256, 0, st>>>(bbase * PP);

            int Gp = 256 / O;
            agg_kernel<<<dim3(PP / Gp, GB), 256, 0, st>>>(
                uwg, ss_s[s], bb_s[s], O, ocoff_s[s], sq, bbase);
        }

        mmagemm<EPI_POOL><<<dim3(4, (GB * PP) / 128, 1), 256, GEMM_SMEM, st>>>(
            xch + (size_t)bbase * PP * 512, xcl + (size_t)bbase * PP * 512, 512, 0, 0,
            w5h, w5l, 512, 0, 0,
            nullptr, 0, 0,
            512, s5, b5, pmax + (size_t)bbase * 8 * 512, psum + (size_t)bbase * 8 * 512);
    }

    cudaEventRecord(evG1, s1s);
    cudaStreamWaitEvent(0, evG1, 0);
    head_kernel<<<BB, 512>>>(L1, s6, b6, L2, bl2, s7, b7, L3, bl3, out);
}

// round 16
// speedup vs baseline: 1.0639x; 1.0639x over previous
#include <cuda_runtime.h>
#include <cuda_bf16.h>
#include <math.h>
#include <stdint.h>

#define BB 16
#define PP 1024
#define KNN 20
#define GB 8            // batches per group (2 groups)

// ---------------- scratch ----------------
__device__ __nv_bfloat16 g_h0h[BB * PP * 128];
__device__ __nv_bfloat16 g_h0l[BB * PP * 128];
__device__ __nv_bfloat16 g_xch[BB * PP * 512];
__device__ __nv_bfloat16 g_xcl[BB * PP * 512];
__device__ float g_uw[BB * PP * 512];              // group g owns [g*GB*PP*512, ...)
__device__ float g_pd[BB * PP * PP];
__device__ int   g_knn[BB * PP * KNN];
__device__ float g_sq[BB * PP];
__device__ float g_pmax[BB * 8 * 512];
__device__ float g_psum[BB * 8 * 512];
__device__ __nv_bfloat16 g_w1h[128 * 128], g_w1l[128 * 128];
__device__ __nv_bfloat16 g_w2h[128 * 64],  g_w2l[128 * 64];
__device__ __nv_bfloat16 g_w3h[256 * 64],  g_w3l[256 * 64];
__device__ __nv_bfloat16 g_w4h[512 * 128], g_w4l[512 * 128];
__device__ __nv_bfloat16 g_w5h[512 * 512], g_w5l[512 * 512];

__device__ __forceinline__ void bsplit(float x, __nv_bfloat16& hi, __nv_bfloat16& lo) {
    hi = __float2bfloat16(x);
    lo = __float2bfloat16(x - __bfloat162float(hi));
}

__device__ __forceinline__ uint32_t smem_u32(const void* p) {
    uint32_t a;
    asm("{ .reg .u64 t; cvta.to.shared.u64 t, %1; cvt.u32.u64 %0, t; }" : "=r"(a) : "l"(p));
    return a;
}

__device__ __forceinline__ void cp_async16(uint32_t dst, const void* src) {
    asm volatile("cp.async.ca.shared.global [%0], [%1], 16;"
                 :: "r"(dst), "l"(__cvta_generic_to_global(src)));
}
#define CP_COMMIT() asm volatile("cp.async.commit_group;")

__device__ __forceinline__ void mma16816(float* c, const uint32_t* a, const uint32_t* b) {
    asm volatile(
        "mma.sync.aligned.m16n8k16.row.col.f32.bf16.bf16.f32 "
        "{%0,%1,%2,%3}, {%4,%5,%6,%7}, {%8,%9}, {%0,%1,%2,%3};"
        : "+f"(c[0]), "+f"(c[1]), "+f"(c[2]), "+f"(c[3])
        : "r"(a[0]), "r"(a[1]), "r"(a[2]), "r"(a[3]), "r"(b[0]), "r"(b[1]));
}

__device__ __forceinline__ void ldsm4(uint32_t addr, uint32_t* r) {
    asm volatile("ldmatrix.sync.aligned.m8n8.x4.shared.b16 {%0,%1,%2,%3}, [%4];"
                 : "=r"(r[0]), "=r"(r[1]), "=r"(r[2]), "=r"(r[3]) : "r"(addr));
}

// ---------------- gather + fused sq: one warp per point ----------------
__global__ void gather_kernel(const float* __restrict__ feats, const int* __restrict__ clusters) {
    int warp = (blockIdx.x * blockDim.x + threadIdx.x) >> 5;   // = bp
    int lane = threadIdx.x & 31;
    if (warp >= BB * PP) return;
    int src = clusters[warp];
    float4 v = __ldg(&reinterpret_cast<const float4*>(feats)[(size_t)src * 32 + lane]);
    size_t e = (size_t)warp * 128 + lane * 4;
    bsplit(v.x, g_h0h[e + 0], g_h0l[e + 0]);
    bsplit(v.y, g_h0h[e + 1], g_h0l[e + 1]);
    bsplit(v.z, g_h0h[e + 2], g_h0l[e + 2]);
    bsplit(v.w, g_h0h[e + 3], g_h0l[e + 3]);
    float s = v.x * v.x + v.y * v.y + v.z * v.z + v.w * v.w;
    #pragma unroll
    for (int o = 16; o; o >>= 1) s += __shfl_xor_sync(0xffffffffu, s, o);
    if (lane == 0) g_sq[warp] = s;
}

// ---------------- merged weight prep ----------------
__global__ void prep_kernel(const float* __restrict__ W1, const float* __restrict__ W2,
                            const float* __restrict__ W3, const float* __restrict__ W4,
                            const float* __restrict__ W5) {
    int t = blockIdx.x * blockDim.x + threadIdx.x;
    if (t < 8192) {
        int o = t / 128, c = t % 128;
        float wa = W1[(size_t)o * 256 + c], wb = W1[(size_t)o * 256 + 128 + c];
        bsplit(wa, g_w1h[o * 128 + c], g_w1l[o * 128 + c]);
        bsplit(wb - wa, g_w1h[(64 + o) * 128 + c], g_w1l[(64 + o) * 128 + c]);
        return;
    }
    t -= 8192;
    if (t < 4096) {
        int o = t / 64, c = t % 64;
        float wa = W2[(size_t)o * 128 + c], wb = W2[(size_t)o * 128 + 64 + c];
        bsplit(wa, g_w2h[o * 64 + c], g_w2l[o * 64 + c]);
        bsplit(wb - wa, g_w2h[(64 + o) * 64 + c], g_w2l[(64 + o) * 64 + c]);
        return;
    }
    t -= 4096;
    if (t < 8192) {
        int o = t / 64, c = t % 64;
        float wa = W3[(size_t)o * 128 + c], wb = W3[(size_t)o * 128 + 64 + c];
        bsplit(wa, g_w3h[o * 64 + c], g_w3l[o * 64 + c]);
        bsplit(wb - wa, g_w3h[(128 + o) * 64 + c], g_w3l[(128 + o) * 64 + c]);
        return;
    }
    t -= 8192;
    if (t < 32768) {
        int o = t / 128, c = t % 128;
        float wa = W4[(size_t)o * 256 + c], wb = W4[(size_t)o * 256 + 128 + c];
        bsplit(wa, g_w4h[o * 128 + c], g_w4l[o * 128 + c]);
        bsplit(wb - wa, g_w4h[(256 + o) * 128 + c], g_w4l[(256 + o) * 128 + c]);
        return;
    }
    t -= 32768;
    if (t < 262144) {
        bsplit(W5[t], g_w5h[t], g_w5l[t]);
    }
}

// ---------------- shared GEMM pieces ----------------
#define EPI_PLAIN 0
#define EPI_POOL  2

#define STRIDE_W 20
#define ROW_B (STRIDE_W * 4)
#define TILE_BYTES (128 * ROW_B)
#define GEMM_SMEM (2 * 4 * TILE_BYTES)

#define GEMM_COMPUTE_S(sAaddr, btoff) \
    { \
        uint32_t ah[2][4], al[2][4]; \
        _Pragma("unroll") \
        for (int mf = 0; mf < 2; mf++) { \
            uint32_t ar = warp_m * 32 + mf * 16 + aoff; \
            uint32_t aaddr = (sAaddr) + ar * ROW_B + s * 32 + achunk * 16; \
            ldsm4(aaddr, ah[mf]); \
            ldsm4(aaddr + TILE_BYTES, al[mf]); \
        } \
        _Pragma("unroll") \
        for (int p = 0; p < 4; p++) { \
            uint32_t nr = warp_n * 64 + (2 * p + bhalf) * 8 + brow; \
            uint32_t baddr = (sAaddr) + (btoff) + nr * ROW_B + s * 32 + bchunk * 16; \
            uint32_t bhp[4], blp[4]; \
            ldsm4(baddr, bhp); \
            ldsm4(baddr + TILE_BYTES, blp); \
            _Pragma("unroll") \
            for (int hf = 0; hf < 2; hf++) { \
                int nf = 2 * p + hf; \
                uint32_t bh2[2] = { bhp[hf * 2], bhp[hf * 2 + 1] }; \
                uint32_t bl2[2] = { blp[hf * 2], blp[hf * 2 + 1] }; \
                _Pragma("unroll") \
                for (int mf = 0; mf < 2; mf++) { \
                    mma16816(acc[mf][nf], ah[mf], bh2); \
                    mma16816(acc[mf][nf], al[mf], bh2); \
                    mma16816(acc[mf][nf], ah[mf], bl2); \
                } \
            } \
        } \
    }

template<int EPI>
__global__ void __launch_bounds__(256)
mmagemm(const __nv_bfloat16* __restrict__ Ahi, const __nv_bfloat16* __restrict__ Alo,
        int lda, long sA, int acoff,
        const __nv_bfloat16* __restrict__ Bhi, const __nv_bfloat16* __restrict__ Blo,
        int ldb, long sB, int bcoff,
        float* __restrict__ Cout, int ldc, long sC,
        int K,
        const float* __restrict__ bn_s, const float* __restrict__ bn_b,
        float* __restrict__ pmax, float* __restrict__ psum) {
    extern __shared__ char dsm[];
    uint32_t smem_base = smem_u32(dsm);
    int tid = threadIdx.x;
    int lane = tid & 31, wid = tid >> 5;
    int warp_m = wid & 3, warp_n = wid >> 2;
    int g = lane >> 2, tid4 = lane & 3;
    int aoff = (lane & 7) + ((lane >> 3) & 1) * 8;
    int achunk = lane >> 4;
    int bhalf = (lane >> 4) & 1;
    int bchunk = (lane >> 3) & 1;
    int brow = lane & 7;
    int b = blockIdx.z;
    Ahi += (size_t)b * sA; Alo += (size_t)b * sA;
    Bhi += (size_t)b * sB; Blo += (size_t)b * sB;
    Cout += (size_t)b * sC;

    size_t aRow = (size_t)blockIdx.y * 128;
    size_t bRow = (size_t)blockIdx.x * 128;
    int nKb = K >> 5;

    float acc[2][8][4];
    #pragma unroll
    for (int mf = 0; mf < 2; mf++)
        #pragma unroll
        for (int nf = 0; nf < 8; nf++)
            #pragma unroll
            for (int i = 0; i < 4; i++) acc[mf][nf][i] = 0.f;

    auto load_block = [&](int buf, int kb) {
        uint32_t sbuf = smem_base + buf * 4 * TILE_BYTES;
        #pragma unroll
        for (int it = 0; it < 8; it++) {
            int i = tid + it * 256;
            int tile = i >> 9;
            int rem = i & 511;
            int row = rem >> 2;
            int chunk = rem & 3;
            uint32_t dst = sbuf + tile * TILE_BYTES + row * ROW_B + chunk * 16;
            const __nv_bfloat16* src;
            if (tile == 0)      src = Ahi + (aRow + row) * lda + acoff + kb * 32 + chunk * 8;
            else if (tile == 1) src = Alo + (aRow + row) * lda + acoff + kb * 32 + chunk * 8;
            else if (tile == 2) src = Bhi + (bRow + row) * ldb + bcoff + kb * 32 + chunk * 8;
            else                src = Blo + (bRow + row) * ldb + bcoff + kb * 32 + chunk * 8;
            cp_async16(dst, src);
        }
        CP_COMMIT();
    };

    load_block(0, 0);
    int buf = 0;
    for (int kb = 0; kb < nKb; kb++) {
        bool pref = (kb + 1 < nKb);
        if (pref) load_block(buf ^ 1, kb + 1);
        if (pref) asm volatile("cp.async.wait_group 1;");
        else      asm volatile("cp.async.wait_group 0;");
        __syncthreads();

        uint32_t sAaddr = smem_base + buf * 4 * TILE_BYTES;
        #pragma unroll
        for (int s = 0; s < 2; s++) {
            GEMM_COMPUTE_S(sAaddr, 2 * TILE_BYTES)
        }
        __syncthreads();
        buf ^= 1;
    }

    if (EPI == EPI_POOL) {
        float tmax[16], tsum[16];
        #pragma unroll
        for (int j = 0; j < 16; j++) { tmax[j] = -INFINITY; tsum[j] = 0.f; }
        #pragma unroll
        for (int nf = 0; nf < 8; nf++) {
            int c = warp_n * 64 + nf * 8 + 2 * tid4;
            float2 cs = *reinterpret_cast<const float2*>(&bn_s[blockIdx.x * 128 + c]);
            float2 cb = *reinterpret_cast<const float2*>(&bn_b[blockIdx.x * 128 + c]);
            #pragma unroll
            for (int mf = 0; mf < 2; mf++) {
                float v0 = acc[mf][nf][0] * cs.x + cb.x; v0 = (v0 > 0.f) ? v0 : 0.2f * v0;
                float v1 = acc[mf][nf][1] * cs.y + cb.y; v1 = (v1 > 0.f) ? v1 : 0.2f * v1;
                float v2 = acc[mf][nf][2] * cs.x + cb.x; v2 = (v2 > 0.f) ? v2 : 0.2f * v2;
                float v3 = acc[mf][nf][3] * cs.y + cb.y; v3 = (v3 > 0.f) ? v3 : 0.2f * v3;
                tmax[nf * 2 + 0] = fmaxf(tmax[nf * 2 + 0], fmaxf(v0, v2));
                tmax[nf * 2 + 1] = fmaxf(tmax[nf * 2 + 1], fmaxf(v1, v3));
                tsum[nf * 2 + 0] += v0 + v2;
                tsum[nf * 2 + 1] += v1 + v3;
            }
        }
        #pragma unroll
        for (int off = 4; off <= 16; off <<= 1) {
            #pragma unroll
            for (int j = 0; j < 16; j++) {
                tmax[j] = fmaxf(tmax[j], __shfl_xor_sync(0xffffffffu, tmax[j], off));
                tsum[j] += __shfl_xor_sync(0xffffffffu, tsum[j], off);
            }
        }
        float* st = (float*)dsm;
        if (g == 0) {
            int base = ((warp_m * 2 + warp_n) * 4 + tid4) * 32;
            #pragma unroll
            for (int j = 0; j < 16; j++) { st[base + j] = tmax[j]; st[base + 16 + j] = tsum[j]; }
        }
        __syncthreads();
        if (warp_m == 0 && g == 0) {
            #pragma unroll
            for (int j = 0; j < 16; j++) {
                float m = -INFINITY, s = 0.f;
                #pragma unroll
                for (int wm = 0; wm < 4; wm++) {
                    int base = ((wm * 2 + warp_n) * 4 + tid4) * 32;
                    m = fmaxf(m, st[base + j]);
                    s += st[base + 16 + j];
                }
                int c = warp_n * 64 + (j >> 1) * 8 + 2 * tid4 + (j & 1);
                pmax[(size_t)blockIdx.y * 512 + blockIdx.x * 128 + c] = m;
                psum[(size_t)blockIdx.y * 512 + blockIdx.x * 128 + c] = s;
            }
        }
    } else {
        #pragma unroll
        for (int mf = 0; mf < 2; mf++) {
            size_t r0 = aRow + warp_m * 32 + mf * 16 + g;
            size_t r1 = r0 + 8;
            #pragma unroll
            for (int nf = 0; nf < 8; nf++) {
                size_t c = (size_t)blockIdx.x * 128 + warp_n * 64 + nf * 8 + 2 * tid4;
                *reinterpret_cast<float2*>(&Cout[r0 * ldc + c]) = make_float2(acc[mf][nf][0], acc[mf][nf][1]);
                *reinterpret_cast<float2*>(&Cout[r1 * ldc + c]) = make_float2(acc[mf][nf][2], acc[mf][nf][3]);
            }
        }
    }
}

// ---------------- symmetric pd GEMM (lower triangle, diag tile sharing, mirrored write) ----------------
__global__ void __launch_bounds__(256)
pdsym(const __nv_bfloat16* __restrict__ Ahi, const __nv_bfloat16* __restrict__ Alo,
      int lda, long sA, int acoff, int K, int bbase) {
    extern __shared__ char dsm[];
    uint32_t smem_base = smem_u32(dsm);
    int tid = threadIdx.x;
    int lane = tid & 31, wid = tid >> 5;
    int warp_m = wid & 3, warp_n = wid >> 2;
    int g = lane >> 2, tid4 = lane & 3;
    int aoff = (lane & 7) + ((lane >> 3) & 1) * 8;
    int achunk = lane >> 4;
    int bhalf = (lane >> 4) & 1;
    int bchunk = (lane >> 3) & 1;
    int brow = lane & 7;
    int b = bbase + blockIdx.z;
    const __nv_bfloat16* Hh = Ahi + (size_t)b * sA;
    const __nv_bfloat16* Hl = Alo + (size_t)b * sA;
    float* pd = g_pd + (size_t)b * PP * PP;
    const float* sqb = g_sq + (size_t)b * PP;

    int t36 = blockIdx.x, by = 0;
    while (t36 > by) { t36 -= by + 1; by++; }
    int bx = t36;
    bool diag = (bx == by);
    uint32_t btoff = diag ? 0u : (uint32_t)(2 * TILE_BYTES);
    int nchunks = diag ? 1024 : 2048;

    size_t aRow = (size_t)by * 128;
    size_t bRow = (size_t)bx * 128;
    int nKb = K >> 5;

    float acc[2][8][4];
    #pragma unroll
    for (int mf = 0; mf < 2; mf++)
        #pragma unroll
        for (int nf = 0; nf < 8; nf++)
            #pragma unroll
            for (int i = 0; i < 4; i++) acc[mf][nf][i] = 0.f;

    auto load_block = [&](int buf, int kb) {
        uint32_t sbuf = smem_base + buf * 4 * TILE_BYTES;
        #pragma unroll
        for (int it = 0; it < 8; it++) {
            int i = tid + it * 256;
            if (i >= nchunks) break;
            int tile = i >> 9;
            int rem = i & 511;
            int row = rem >> 2;
            int chunk = rem & 3;
            uint32_t dst = sbuf + tile * TILE_BYTES + row * ROW_B + chunk * 16;
            const __nv_bfloat16* src;
            if (tile == 0)      src = Hh + (aRow + row) * lda + acoff + kb * 32 + chunk * 8;
            else if (tile == 1) src = Hl + (aRow + row) * lda + acoff + kb * 32 + chunk * 8;
            else if (tile == 2) src = Hh + (bRow + row) * lda + acoff + kb * 32 + chunk * 8;
            else                src = Hl + (bRow + row) * lda + acoff + kb * 32 + chunk * 8;
            cp_async16(dst, src);
        }
        CP_COMMIT();
    };

    load_block(0, 0);
    int buf = 0;
    for (int kb = 0; kb < nKb; kb++) {
        bool pref = (kb + 1 < nKb);
        if (pref) load_block(buf ^ 1, kb + 1);
        if (pref) asm volatile("cp.async.wait_group 1;");
        else      asm volatile("cp.async.wait_group 0;");
        __syncthreads();

        uint32_t sAaddr = smem_base + buf * 4 * TILE_BYTES;
        #pragma unroll
        for (int s = 0; s < 2; s++) {
            GEMM_COMPUTE_S(sAaddr, btoff)
        }
        __syncthreads();
        buf ^= 1;
    }

    #pragma unroll
    for (int mf = 0; mf < 2; mf++) {
        size_t r0 = aRow + warp_m * 32 + mf * 16 + g;
        size_t r1 = r0 + 8;
        #pragma unroll
        for (int nf = 0; nf < 8; nf++) {
            size_t c = bRow + warp_n * 64 + nf * 8 + 2 * tid4;
            float2 cs = *reinterpret_cast<const float2*>(&sqb[c]);
            *reinterpret_cast<float2*>(&pd[r0 * PP + c]) =
                make_float2(2.f * acc[mf][nf][0] - cs.x, 2.f * acc[mf][nf][1] - cs.y);
            *reinterpret_cast<float2*>(&pd[r1 * PP + c]) =
                make_float2(2.f * acc[mf][nf][2] - cs.x, 2.f * acc[mf][nf][3] - cs.y);
        }
    }

    if (!diag) {
        float* st = (float*)dsm;
        #pragma unroll
        for (int mf = 0; mf < 2; mf++) {
            int rl0 = warp_m * 32 + mf * 16 + g;
            int rl1 = rl0 + 8;
            #pragma unroll
            for (int nf = 0; nf < 8; nf++) {
                int cl = warp_n * 64 + nf * 8 + 2 * tid4;
                st[rl0 * 129 + cl]     = 2.f * acc[mf][nf][0];
                st[rl0 * 129 + cl + 1] = 2.f * acc[mf][nf][1];
                st[rl1 * 129 + cl]     = 2.f * acc[mf][nf][2];
                st[rl1 * 129 + cl + 1] = 2.f * acc[mf][nf][3];
            }
        }
        __syncthreads();
        for (int i = tid; i < 128 * 32; i += 256) {
            int cl = i >> 5;
            int r  = (i & 31) * 4;
            float4 sv;
            sv.x = st[(r + 0) * 129 + cl];
            sv.y = st[(r + 1) * 129 + cl];
            sv.z = st[(r + 2) * 129 + cl];
            sv.w = st[(r + 3) * 129 + cl];
            float4 sq4 = *reinterpret_cast<const float4*>(&sqb[aRow + r]);
            float4 o = make_float4(sv.x - sq4.x, sv.y - sq4.y, sv.z - sq4.z, sv.w - sq4.w);
            *reinterpret_cast<float4*>(&pd[(bRow + cl) * PP + aRow + r]) = o;
        }
    }
}

// ---------------- top-20 per row: register-resident (R14 strided loads) ----------------
__global__ void __launch_bounds__(256) topk_kernel(int rowbase) {
    int warp = threadIdx.x >> 5, lane = threadIdx.x & 31;
    int row = rowbase + blockIdx.x * 8 + warp;
    const float* __restrict__ prow = g_pd + (size_t)row * PP;

    float v[32];
    #pragma unroll
    for (int slot = 0; slot < 32; slot++) v[slot] = __ldg(&prow[slot * 32 + lane]);

    float m1 = -INFINITY, m2 = -INFINITY;
    int i1 = PP, i2 = PP;
    #pragma unroll
    for (int slot = 0; slot < 32; slot++) {
        float x = v[slot];
        int j = slot * 32 + lane;
        if (x > m1) { m2 = m1; i2 = i1; m1 = x; i1 = j; }
        else if (x > m2) { m2 = x; i2 = j; }
    }
    bool have2 = true;
    unsigned mask = 0;

    for (int k = 0; k < KNN; k++) {
        float best = m1; int bi = i1;
        #pragma unroll
        for (int o = 16; o; o >>= 1) {
            float ov = __shfl_xor_sync(0xffffffffu, best, o);
            int   oi = __shfl_xor_sync(0xffffffffu, bi, o);
            if (ov > best || (ov == best && oi < bi)) { best = ov; bi = oi; }
        }
        if (lane == 0) g_knn[row * KNN + k] = bi;
        if (i1 == bi) {
            mask |= 1u << (bi >> 5);
            if (have2) { m1 = m2; i1 = i2; have2 = false; }
            else {
                m1 = -INFINITY; m2 = -INFINITY; i1 = PP; i2 = PP;
                #pragma unroll
                for (int slot = 0; slot < 32; slot++) {
                    if (!(mask & (1u << slot))) {
                        float x = v[slot];
                        int j = slot * 32 + lane;
                        if (x > m1) { m2 = m1; i2 = i1; m1 = x; i1 = j; }
                        else if (x > m2) { m2 = x; i2 = j; }
                    }
                }
                have2 = true;
            }
        }
    }
}

// ---------------- aggregate + fused next-stage sq + bf16 split output ----------------
__global__ void __launch_bounds__(256) agg_kernel(
    const float* __restrict__ uw,
    const float* __restrict__ s, const float* __restrict__ bias,
    int O, int coloff, float* __restrict__ sqout, int bbase) {
    __shared__ int sidx[128];
    __shared__ float red[256];
    int tid = threadIdx.x;
    int G = 256 / O;
    int pi = tid / O;
    int o = tid - pi * O;
    int bl = blockIdx.y;
    int b = bbase + bl;
    int p = blockIdx.x * G + pi;
    size_t base = (size_t)b * PP + p;

    if (tid < G * KNN) {
        int gp = tid / KNN, kk = tid - gp * KNN;
        sidx[tid] = g_knn[((size_t)b * PP + blockIdx.x * G + gp) * KNN + kk];
    }
    __syncthreads();

    int twoO = 2 * O;
    const float* __restrict__ ub = uw + (size_t)bl * PP * twoO;
    float wv = __ldg(&ub[(size_t)p * twoO + O + o]);
    float sv = s[o], bv = bias[o];
    const int* idx = sidx + pi * KNN;
    float m = -INFINITY;
    #pragma unroll
    for (int k = 0; k < KNN; k++) {
        int nb = idx[k];
        float y = __ldg(&ub[(size_t)nb * twoO + o]) + wv;
        y = y * sv + bv;
        y = (y > 0.f) ? y : 0.2f * y;
        m = fmaxf(m, y);
    }
    bsplit(m, g_xch[base * 512 + coloff + o], g_xcl[base * 512 + coloff + o]);

    red[tid] = m * m;
    __syncthreads();
    for (int st = O >> 1; st > 0; st >>= 1) {
        if (o < st) red[tid] += red[tid + st];
        __syncthreads();
    }
    if (o == 0) sqout[base] = red[tid];
}

// ---------------- MLP head (with inline pool combine) ----------------
__global__ void head_kernel(const float* __restrict__ L1, const float* __restrict__ s6, const float* __restrict__ b6,
                            const float* __restrict__ L2, const float* __restrict__ bl2,
                            const float* __restrict__ s7, const float* __restrict__ b7,
                            const float* __restrict__ L3, const float* __restrict__ bl3,
                            float* __restrict__ out) {
    __shared__ float sf[1024];
    __shared__ float z1[512];
    __shared__ float z2[256];
    int b = blockIdx.x, t = threadIdx.x;
    {
        float mx = -INFINITY, sm = 0.f;
        #pragma unroll
        for (int c = 0; c < 8; c++) {
            mx = fmaxf(mx, g_pmax[(b * 8 + c) * 512 + t]);
            sm += g_psum[(b * 8 + c) * 512 + t];
        }
        sf[t] = mx;
        sf[t + 512] = sm * (1.0f / PP);
    }
    __syncthreads();
    {
        float a = 0.f;
        const float* r = L1 + (size_t)t * 1024;
        for (int j = 0; j < 1024; j++) a += sf[j] * r[j];
        a = a * s6[t] + b6[t];
        z1[t] = (a > 0.f) ? a : 0.2f * a;
    }
    __syncthreads();
    if (t < 256) {
        float a = 0.f;
        const float* r = L2 + (size_t)t * 512;
        for (int j = 0; j < 512; j++) a += z1[j] * r[j];
        a = (a + bl2[t]) * s7[t] + b7[t];
        a = (a > 0.f) ? a : 0.2f * a;
        z2[t] = a * L3[t];
    }
    __syncthreads();
    if (t < 128) z2[t] += z2[t + 128];
    __syncthreads();
    if (t < 64) z2[t] += z2[t + 64];
    __syncthreads();
    if (t < 32) {
        float v = z2[t] + z2[t + 32];
        #pragma unroll
        for (int o = 16; o; o >>= 1) v += __shfl_down_sync(0xffffffffu, v, o);
        if (t == 0) {
            float z = v + bl3[0];
            out[b] = 1.0f / (1.0f + expf(-z));
        }
    }
}

// ---------------- host orchestration (R14 schedule) ----------------
extern "C" void kernel_launch(void* const* d_in, const int* in_sizes, int n_in,
                              void* d_out, int out_size) {
    const int* clusters;
    const float* features;
    if (in_sizes[0] == BB * PP) {
        clusters = (const int*)d_in[0];
        features = (const float*)d_in[1];
    } else {
        features = (const float*)d_in[0];
        clusters = (const int*)d_in[1];
    }
    const float* W1  = (const float*)d_in[2];
    const float* s1p = (const float*)d_in[3];
    const float* b1  = (const float*)d_in[4];
    const float* W2  = (const float*)d_in[5];
    const float* s2  = (const float*)d_in[6];
    const float* b2  = (const float*)d_in[7];
    const float* W3  = (const float*)d_in[8];
    const float* s3  = (const float*)d_in[9];
    const float* b3  = (const float*)d_in[10];
    const float* W4  = (const float*)d_in[11];
    const float* s4  = (const float*)d_in[12];
    const float* b4  = (const float*)d_in[13];
    const float* W5  = (const float*)d_in[14];
    const float* s5  = (const float*)d_in[15];
    const float* b5  = (const float*)d_in[16];
    const float* L1  = (const float*)d_in[17];
    const float* s6  = (const float*)d_in[18];
    const float* b6  = (const float*)d_in[19];
    const float* L2  = (const float*)d_in[20];
    const float* bl2 = (const float*)d_in[21];
    const float* s7  = (const float*)d_in[22];
    const float* b7  = (const float*)d_in[23];
    const float* L3  = (const float*)d_in[24];
    const float* bl3 = (const float*)d_in[25];
    float* out = (float*)d_out;

    static cudaStream_t s1s = nullptr;
    static cudaEvent_t evRoot, evA, evP, evG1;
    if (!s1s) {
        cudaFuncSetAttribute(mmagemm<EPI_PLAIN>, cudaFuncAttributeMaxDynamicSharedMemorySize, GEMM_SMEM);
        cudaFuncSetAttribute(mmagemm<EPI_POOL>,  cudaFuncAttributeMaxDynamicSharedMemorySize, GEMM_SMEM);
        cudaFuncSetAttribute(pdsym,              cudaFuncAttributeMaxDynamicSharedMemorySize, GEMM_SMEM);
        cudaStreamCreateWithFlags(&s1s, cudaStreamNonBlocking);
        cudaEventCreateWithFlags(&evRoot, cudaEventDisableTiming);
        cudaEventCreateWithFlags(&evA, cudaEventDisableTiming);
        cudaEventCreateWithFlags(&evP, cudaEventDisableTiming);
        cudaEventCreateWithFlags(&evG1, cudaEventDisableTiming);
    }

    float *uw, *sq, *pmax, *psum;
    __nv_bfloat16 *h0h, *h0l, *xch, *xcl;
    __nv_bfloat16 *w1h, *w1l, *w2h, *w2l, *w3h, *w3l, *w4h, *w4l, *w5h, *w5l;
    cudaGetSymbolAddress((void**)&uw, g_uw);
    cudaGetSymbolAddress((void**)&sq, g_sq);
    cudaGetSymbolAddress((void**)&pmax, g_pmax);
    cudaGetSymbolAddress((void**)&psum, g_psum);
    cudaGetSymbolAddress((void**)&h0h, g_h0h);
    cudaGetSymbolAddress((void**)&h0l, g_h0l);
    cudaGetSymbolAddress((void**)&xch, g_xch);
    cudaGetSymbolAddress((void**)&xcl, g_xcl);
    cudaGetSymbolAddress((void**)&w1h, g_w1h); cudaGetSymbolAddress((void**)&w1l, g_w1l);
    cudaGetSymbolAddress((void**)&w2h, g_w2h); cudaGetSymbolAddress((void**)&w2l, g_w2l);
    cudaGetSymbolAddress((void**)&w3h, g_w3h); cudaGetSymbolAddress((void**)&w3l, g_w3l);
    cudaGetSymbolAddress((void**)&w4h, g_w4h); cudaGetSymbolAddress((void**)&w4l, g_w4l);
    cudaGetSymbolAddress((void**)&w5h, g_w5h); cudaGetSymbolAddress((void**)&w5l, g_w5l);

    const __nv_bfloat16* hh[4] = { h0h, xch, xch, xch };
    const __nv_bfloat16* hl[4] = { h0l, xcl, xcl, xcl };
    int lda_s[4]   = { 128, 512, 512, 512 };
    int coff_s[4]  = { 0, 0, 64, 128 };
    int C_s[4]     = { 128, 64, 64, 128 };
    int O_s[4]     = { 64, 64, 128, 256 };
    const __nv_bfloat16* wh_s[4] = { w1h, w2h, w3h, w4h };
    const __nv_bfloat16* wl_s[4] = { w1l, w2l, w3l, w4l };
    const float* ss_s[4] = { s1p, s2, s3, s4 };
    const float* bb_s[4] = { b1, b2, b3, b4 };
    int ocoff_s[4] = { 0, 64, 128, 256 };

    // fork: prep on side stream
    cudaEventRecord(evRoot, 0);
    cudaStreamWaitEvent(s1s, evRoot, 0);
    prep_kernel<<<(8192 + 4096 + 8192 + 32768 + 262144 + 255) / 256, 256, 0, s1s>>>(W1, W2, W3, W4, W5);
    cudaEventRecord(evP, s1s);

    // gather + fused sq (warp per point)
    gather_kernel<<<BB * PP / 8, 256>>>(features, clusters);
    cudaEventRecord(evA, 0);

    cudaStreamWaitEvent(0, evP, 0);
    cudaStreamWaitEvent(s1s, evA, 0);

    cudaStream_t streams[2] = { 0, s1s };
    for (int grp = 0; grp < 2; grp++) {
        cudaStream_t st = streams[grp];
        int bbase = grp * GB;
        float* uwg = uw + (size_t)grp * GB * PP * 512;

        for (int s = 0; s < 4; s++) {
            long strideA = (long)PP * lda_s[s];
            int C = C_s[s], O = O_s[s];
            size_t hoff = (size_t)bbase * PP * lda_s[s];

            mmagemm<EPI_PLAIN><<<dim3((2 * O) / 128, (GB * PP) / 128, 1), 256, GEMM_SMEM, st>>>(
                hh[s] + hoff, hl[s] + hoff, lda_s[s], 0, coff_s[s],
                wh_s[s], wl_s[s], C, 0, 0,
                uwg, 2 * O, 0,
                C, nullptr, nullptr, nullptr, nullptr);

            pdsym<<<dim3(36, 1, GB), 256, GEMM_SMEM, st>>>(
                hh[s], hl[s], lda_s[s], strideA, coff_s[s], C, bbase);

            topk_kernel<<<GB * PP / 8, 256, 0, st>>>(bbase * PP);

            int Gp = 256 / O;
            agg_kernel<<<dim3(PP / Gp, GB), 256, 0, st>>>(
                uwg, ss_s[s], bb_s[s], O, ocoff_s[s], sq, bbase);
        }

        mmagemm<EPI_POOL><<<dim3(4, (GB * PP) / 128, 1), 256, GEMM_SMEM, st>>>(
            xch + (size_t)bbase * PP * 512, xcl + (size_t)bbase * PP * 512, 512, 0, 0,
            w5h, w5l, 512, 0, 0,
            nullptr, 0, 0,
            512, s5, b5, pmax + (size_t)bbase * 8 * 512, psum + (size_t)bbase * 8 * 512);
    }

    cudaEventRecord(evG1, s1s);
    cudaStreamWaitEvent(0, evG1, 0);
    head_kernel<<<BB, 512>>>(L1, s6, b6, L2, bl2, s7, b7, L3, bl3, out);
}

// round 17
// speedup vs baseline: 1.4378x; 1.3515x over previous
#include <cuda_runtime.h>
#include <cuda_bf16.h>
#include <math.h>
#include <stdint.h>

#define BB 16
#define PP 1024
#define KNN 20
#define GB 8            // batches per group (2 groups)

// ---------------- scratch ----------------
__device__ __nv_bfloat16 g_h0h[BB * PP * 128];
__device__ __nv_bfloat16 g_h0l[BB * PP * 128];
__device__ __nv_bfloat16 g_xch[BB * PP * 512];
__device__ __nv_bfloat16 g_xcl[BB * PP * 512];
__device__ float g_uw[BB * PP * 512];              // group g owns [g*GB*PP*512, ...)
__device__ float g_pd[BB * PP * PP];
__device__ int   g_knn[BB * PP * KNN];
__device__ float g_sq[BB * PP];
__device__ float g_pmax[BB * 8 * 512];
__device__ float g_psum[BB * 8 * 512];
__device__ __nv_bfloat16 g_w1h[128 * 128], g_w1l[128 * 128];
__device__ __nv_bfloat16 g_w2h[128 * 64],  g_w2l[128 * 64];
__device__ __nv_bfloat16 g_w3h[256 * 64],  g_w3l[256 * 64];
__device__ __nv_bfloat16 g_w4h[512 * 128], g_w4l[512 * 128];
__device__ __nv_bfloat16 g_w5h[512 * 512], g_w5l[512 * 512];

__device__ __forceinline__ void bsplit(float x, __nv_bfloat16& hi, __nv_bfloat16& lo) {
    hi = __float2bfloat16(x);
    lo = __float2bfloat16(x - __bfloat162float(hi));
}

__device__ __forceinline__ uint32_t smem_u32(const void* p) {
    uint32_t a;
    asm("{ .reg .u64 t; cvta.to.shared.u64 t, %1; cvt.u32.u64 %0, t; }" : "=r"(a) : "l"(p));
    return a;
}

__device__ __forceinline__ void cp_async16(uint32_t dst, const void* src) {
    asm volatile("cp.async.ca.shared.global [%0], [%1], 16;"
                 :: "r"(dst), "l"(__cvta_generic_to_global(src)));
}
#define CP_COMMIT() asm volatile("cp.async.commit_group;")

__device__ __forceinline__ void mma16816(float* c, const uint32_t* a, const uint32_t* b) {
    asm volatile(
        "mma.sync.aligned.m16n8k16.row.col.f32.bf16.bf16.f32 "
        "{%0,%1,%2,%3}, {%4,%5,%6,%7}, {%8,%9}, {%0,%1,%2,%3};"
        : "+f"(c[0]), "+f"(c[1]), "+f"(c[2]), "+f"(c[3])
        : "r"(a[0]), "r"(a[1]), "r"(a[2]), "r"(a[3]), "r"(b[0]), "r"(b[1]));
}

__device__ __forceinline__ void ldsm4(uint32_t addr, uint32_t* r) {
    asm volatile("ldmatrix.sync.aligned.m8n8.x4.shared.b16 {%0,%1,%2,%3}, [%4];"
                 : "=r"(r[0]), "=r"(r[1]), "=r"(r[2]), "=r"(r[3]) : "r"(addr));
}

// ---------------- gather + fused sq: one warp per point ----------------
__global__ void gather_kernel(const float* __restrict__ feats, const int* __restrict__ clusters) {
    int warp = (blockIdx.x * blockDim.x + threadIdx.x) >> 5;   // = bp
    int lane = threadIdx.x & 31;
    if (warp >= BB * PP) return;
    int src = clusters[warp];
    float4 v = __ldg(&reinterpret_cast<const float4*>(feats)[(size_t)src * 32 + lane]);
    size_t e = (size_t)warp * 128 + lane * 4;
    bsplit(v.x, g_h0h[e + 0], g_h0l[e + 0]);
    bsplit(v.y, g_h0h[e + 1], g_h0l[e + 1]);
    bsplit(v.z, g_h0h[e + 2], g_h0l[e + 2]);
    bsplit(v.w, g_h0h[e + 3], g_h0l[e + 3]);
    float s = v.x * v.x + v.y * v.y + v.z * v.z + v.w * v.w;
    #pragma unroll
    for (int o = 16; o; o >>= 1) s += __shfl_xor_sync(0xffffffffu, s, o);
    if (lane == 0) g_sq[warp] = s;
}

// ---------------- merged weight prep ----------------
__global__ void prep_kernel(const float* __restrict__ W1, const float* __restrict__ W2,
                            const float* __restrict__ W3, const float* __restrict__ W4,
                            const float* __restrict__ W5) {
    int t = blockIdx.x * blockDim.x + threadIdx.x;
    if (t < 8192) {
        int o = t / 128, c = t % 128;
        float wa = W1[(size_t)o * 256 + c], wb = W1[(size_t)o * 256 + 128 + c];
        bsplit(wa, g_w1h[o * 128 + c], g_w1l[o * 128 + c]);
        bsplit(wb - wa, g_w1h[(64 + o) * 128 + c], g_w1l[(64 + o) * 128 + c]);
        return;
    }
    t -= 8192;
    if (t < 4096) {
        int o = t / 64, c = t % 64;
        float wa = W2[(size_t)o * 128 + c], wb = W2[(size_t)o * 128 + 64 + c];
        bsplit(wa, g_w2h[o * 64 + c], g_w2l[o * 64 + c]);
        bsplit(wb - wa, g_w2h[(64 + o) * 64 + c], g_w2l[(64 + o) * 64 + c]);
        return;
    }
    t -= 4096;
    if (t < 8192) {
        int o = t / 64, c = t % 64;
        float wa = W3[(size_t)o * 128 + c], wb = W3[(size_t)o * 128 + 64 + c];
        bsplit(wa, g_w3h[o * 64 + c], g_w3l[o * 64 + c]);
        bsplit(wb - wa, g_w3h[(128 + o) * 64 + c], g_w3l[(128 + o) * 64 + c]);
        return;
    }
    t -= 8192;
    if (t < 32768) {
        int o = t / 128, c = t % 128;
        float wa = W4[(size_t)o * 256 + c], wb = W4[(size_t)o * 256 + 128 + c];
        bsplit(wa, g_w4h[o * 128 + c], g_w4l[o * 128 + c]);
        bsplit(wb - wa, g_w4h[(256 + o) * 128 + c], g_w4l[(256 + o) * 128 + c]);
        return;
    }
    t -= 32768;
    if (t < 262144) {
        bsplit(W5[t], g_w5h[t], g_w5l[t]);
    }
}

// ---------------- shared GEMM pieces ----------------
#define EPI_PLAIN 0
#define EPI_POOL  2

#define STRIDE_W 20
#define ROW_B (STRIDE_W * 4)
#define TILE_BYTES (128 * ROW_B)
#define GEMM_SMEM (2 * 4 * TILE_BYTES)

#define GEMM_COMPUTE_S(sAaddr, btoff) \
    { \
        uint32_t ah[2][4], al[2][4]; \
        _Pragma("unroll") \
        for (int mf = 0; mf < 2; mf++) { \
            uint32_t ar = warp_m * 32 + mf * 16 + aoff; \
            uint32_t aaddr = (sAaddr) + ar * ROW_B + s * 32 + achunk * 16; \
            ldsm4(aaddr, ah[mf]); \
            ldsm4(aaddr + TILE_BYTES, al[mf]); \
        } \
        _Pragma("unroll") \
        for (int p = 0; p < 4; p++) { \
            uint32_t nr = warp_n * 64 + (2 * p + bhalf) * 8 + brow; \
            uint32_t baddr = (sAaddr) + (btoff) + nr * ROW_B + s * 32 + bchunk * 16; \
            uint32_t bhp[4], blp[4]; \
            ldsm4(baddr, bhp); \
            ldsm4(baddr + TILE_BYTES, blp); \
            _Pragma("unroll") \
            for (int hf = 0; hf < 2; hf++) { \
                int nf = 2 * p + hf; \
                uint32_t bh2[2] = { bhp[hf * 2], bhp[hf * 2 + 1] }; \
                uint32_t bl2[2] = { blp[hf * 2], blp[hf * 2 + 1] }; \
                _Pragma("unroll") \
                for (int mf = 0; mf < 2; mf++) { \
                    mma16816(acc[mf][nf], ah[mf], bh2); \
                    mma16816(acc[mf][nf], al[mf], bh2); \
                    mma16816(acc[mf][nf], ah[mf], bl2); \
                } \
            } \
        } \
    }

template<int EPI>
__global__ void __launch_bounds__(256)
mmagemm(const __nv_bfloat16* __restrict__ Ahi, const __nv_bfloat16* __restrict__ Alo,
        int lda, long sA, int acoff,
        const __nv_bfloat16* __restrict__ Bhi, const __nv_bfloat16* __restrict__ Blo,
        int ldb, long sB, int bcoff,
        float* __restrict__ Cout, int ldc, long sC,
        int K,
        const float* __restrict__ bn_s, const float* __restrict__ bn_b,
        float* __restrict__ pmax, float* __restrict__ psum) {
    extern __shared__ char dsm[];
    uint32_t smem_base = smem_u32(dsm);
    int tid = threadIdx.x;
    int lane = tid & 31, wid = tid >> 5;
    int warp_m = wid & 3, warp_n = wid >> 2;
    int g = lane >> 2, tid4 = lane & 3;
    int aoff = (lane & 7) + ((lane >> 3) & 1) * 8;
    int achunk = lane >> 4;
    int bhalf = (lane >> 4) & 1;
    int bchunk = (lane >> 3) & 1;
    int brow = lane & 7;
    int b = blockIdx.z;
    Ahi += (size_t)b * sA; Alo += (size_t)b * sA;
    Bhi += (size_t)b * sB; Blo += (size_t)b * sB;
    Cout += (size_t)b * sC;

    size_t aRow = (size_t)blockIdx.y * 128;
    size_t bRow = (size_t)blockIdx.x * 128;
    int nKb = K >> 5;

    float acc[2][8][4];
    #pragma unroll
    for (int mf = 0; mf < 2; mf++)
        #pragma unroll
        for (int nf = 0; nf < 8; nf++)
            #pragma unroll
            for (int i = 0; i < 4; i++) acc[mf][nf][i] = 0.f;

    auto load_block = [&](int buf, int kb) {
        uint32_t sbuf = smem_base + buf * 4 * TILE_BYTES;
        #pragma unroll
        for (int it = 0; it < 8; it++) {
            int i = tid + it * 256;
            int tile = i >> 9;
            int rem = i & 511;
            int row = rem >> 2;
            int chunk = rem & 3;
            uint32_t dst = sbuf + tile * TILE_BYTES + row * ROW_B + chunk * 16;
            const __nv_bfloat16* src;
            if (tile == 0)      src = Ahi + (aRow + row) * lda + acoff + kb * 32 + chunk * 8;
            else if (tile == 1) src = Alo + (aRow + row) * lda + acoff + kb * 32 + chunk * 8;
            else if (tile == 2) src = Bhi + (bRow + row) * ldb + bcoff + kb * 32 + chunk * 8;
            else                src = Blo + (bRow + row) * ldb + bcoff + kb * 32 + chunk * 8;
            cp_async16(dst, src);
        }
        CP_COMMIT();
    };

    load_block(0, 0);
    int buf = 0;
    for (int kb = 0; kb < nKb; kb++) {
        bool pref = (kb + 1 < nKb);
        if (pref) load_block(buf ^ 1, kb + 1);
        if (pref) asm volatile("cp.async.wait_group 1;");
        else      asm volatile("cp.async.wait_group 0;");
        __syncthreads();

        uint32_t sAaddr = smem_base + buf * 4 * TILE_BYTES;
        #pragma unroll
        for (int s = 0; s < 2; s++) {
            GEMM_COMPUTE_S(sAaddr, 2 * TILE_BYTES)
        }
        __syncthreads();
        buf ^= 1;
    }

    if (EPI == EPI_POOL) {
        float tmax[16], tsum[16];
        #pragma unroll
        for (int j = 0; j < 16; j++) { tmax[j] = -INFINITY; tsum[j] = 0.f; }
        #pragma unroll
        for (int nf = 0; nf < 8; nf++) {
            int c = warp_n * 64 + nf * 8 + 2 * tid4;
            float2 cs = *reinterpret_cast<const float2*>(&bn_s[blockIdx.x * 128 + c]);
            float2 cb = *reinterpret_cast<const float2*>(&bn_b[blockIdx.x * 128 + c]);
            #pragma unroll
            for (int mf = 0; mf < 2; mf++) {
                float v0 = acc[mf][nf][0] * cs.x + cb.x; v0 = (v0 > 0.f) ? v0 : 0.2f * v0;
                float v1 = acc[mf][nf][1] * cs.y + cb.y; v1 = (v1 > 0.f) ? v1 : 0.2f * v1;
                float v2 = acc[mf][nf][2] * cs.x + cb.x; v2 = (v2 > 0.f) ? v2 : 0.2f * v2;
                float v3 = acc[mf][nf][3] * cs.y + cb.y; v3 = (v3 > 0.f) ? v3 : 0.2f * v3;
                tmax[nf * 2 + 0] = fmaxf(tmax[nf * 2 + 0], fmaxf(v0, v2));
                tmax[nf * 2 + 1] = fmaxf(tmax[nf * 2 + 1], fmaxf(v1, v3));
                tsum[nf * 2 + 0] += v0 + v2;
                tsum[nf * 2 + 1] += v1 + v3;
            }
        }
        #pragma unroll
        for (int off = 4; off <= 16; off <<= 1) {
            #pragma unroll
            for (int j = 0; j < 16; j++) {
                tmax[j] = fmaxf(tmax[j], __shfl_xor_sync(0xffffffffu, tmax[j], off));
                tsum[j] += __shfl_xor_sync(0xffffffffu, tsum[j], off);
            }
        }
        float* st = (float*)dsm;
        if (g == 0) {
            int base = ((warp_m * 2 + warp_n) * 4 + tid4) * 32;
            #pragma unroll
            for (int j = 0; j < 16; j++) { st[base + j] = tmax[j]; st[base + 16 + j] = tsum[j]; }
        }
        __syncthreads();
        if (warp_m == 0 && g == 0) {
            #pragma unroll
            for (int j = 0; j < 16; j++) {
                float m = -INFINITY, s = 0.f;
                #pragma unroll
                for (int wm = 0; wm < 4; wm++) {
                    int base = ((wm * 2 + warp_n) * 4 + tid4) * 32;
                    m = fmaxf(m, st[base + j]);
                    s += st[base + 16 + j];
                }
                int c = warp_n * 64 + (j >> 1) * 8 + 2 * tid4 + (j & 1);
                pmax[(size_t)blockIdx.y * 512 + blockIdx.x * 128 + c] = m;
                psum[(size_t)blockIdx.y * 512 + blockIdx.x * 128 + c] = s;
            }
        }
    } else {
        #pragma unroll
        for (int mf = 0; mf < 2; mf++) {
            size_t r0 = aRow + warp_m * 32 + mf * 16 + g;
            size_t r1 = r0 + 8;
            #pragma unroll
            for (int nf = 0; nf < 8; nf++) {
                size_t c = (size_t)blockIdx.x * 128 + warp_n * 64 + nf * 8 + 2 * tid4;
                *reinterpret_cast<float2*>(&Cout[r0 * ldc + c]) = make_float2(acc[mf][nf][0], acc[mf][nf][1]);
                *reinterpret_cast<float2*>(&Cout[r1 * ldc + c]) = make_float2(acc[mf][nf][2], acc[mf][nf][3]);
            }
        }
    }
}

// ---------------- symmetric pd GEMM (lower triangle, diag tile sharing, mirrored write) ----------------
__global__ void __launch_bounds__(256)
pdsym(const __nv_bfloat16* __restrict__ Ahi, const __nv_bfloat16* __restrict__ Alo,
      int lda, long sA, int acoff, int K, int bbase) {
    extern __shared__ char dsm[];
    uint32_t smem_base = smem_u32(dsm);
    int tid = threadIdx.x;
    int lane = tid & 31, wid = tid >> 5;
    int warp_m = wid & 3, warp_n = wid >> 2;
    int g = lane >> 2, tid4 = lane & 3;
    int aoff = (lane & 7) + ((lane >> 3) & 1) * 8;
    int achunk = lane >> 4;
    int bhalf = (lane >> 4) & 1;
    int bchunk = (lane >> 3) & 1;
    int brow = lane & 7;
    int b = bbase + blockIdx.z;
    const __nv_bfloat16* Hh = Ahi + (size_t)b * sA;
    const __nv_bfloat16* Hl = Alo + (size_t)b * sA;
    float* pd = g_pd + (size_t)b * PP * PP;
    const float* sqb = g_sq + (size_t)b * PP;

    int t36 = blockIdx.x, by = 0;
    while (t36 > by) { t36 -= by + 1; by++; }
    int bx = t36;
    bool diag = (bx == by);
    uint32_t btoff = diag ? 0u : (uint32_t)(2 * TILE_BYTES);
    int nchunks = diag ? 1024 : 2048;

    size_t aRow = (size_t)by * 128;
    size_t bRow = (size_t)bx * 128;
    int nKb = K >> 5;

    float acc[2][8][4];
    #pragma unroll
    for (int mf = 0; mf < 2; mf++)
        #pragma unroll
        for (int nf = 0; nf < 8; nf++)
            #pragma unroll
            for (int i = 0; i < 4; i++) acc[mf][nf][i] = 0.f;

    auto load_block = [&](int buf, int kb) {
        uint32_t sbuf = smem_base + buf * 4 * TILE_BYTES;
        #pragma unroll
        for (int it = 0; it < 8; it++) {
            int i = tid + it * 256;
            if (i >= nchunks) break;
            int tile = i >> 9;
            int rem = i & 511;
            int row = rem >> 2;
            int chunk = rem & 3;
            uint32_t dst = sbuf + tile * TILE_BYTES + row * ROW_B + chunk * 16;
            const __nv_bfloat16* src;
            if (tile == 0)      src = Hh + (aRow + row) * lda + acoff + kb * 32 + chunk * 8;
            else if (tile == 1) src = Hl + (aRow + row) * lda + acoff + kb * 32 + chunk * 8;
            else if (tile == 2) src = Hh + (bRow + row) * lda + acoff + kb * 32 + chunk * 8;
            else                src = Hl + (bRow + row) * lda + acoff + kb * 32 + chunk * 8;
            cp_async16(dst, src);
        }
        CP_COMMIT();
    };

    load_block(0, 0);
    int buf = 0;
    for (int kb = 0; kb < nKb; kb++) {
        bool pref = (kb + 1 < nKb);
        if (pref) load_block(buf ^ 1, kb + 1);
        if (pref) asm volatile("cp.async.wait_group 1;");
        else      asm volatile("cp.async.wait_group 0;");
        __syncthreads();

        uint32_t sAaddr = smem_base + buf * 4 * TILE_BYTES;
        #pragma unroll
        for (int s = 0; s < 2; s++) {
            GEMM_COMPUTE_S(sAaddr, btoff)
        }
        __syncthreads();
        buf ^= 1;
    }

    #pragma unroll
    for (int mf = 0; mf < 2; mf++) {
        size_t r0 = aRow + warp_m * 32 + mf * 16 + g;
        size_t r1 = r0 + 8;
        #pragma unroll
        for (int nf = 0; nf < 8; nf++) {
            size_t c = bRow + warp_n * 64 + nf * 8 + 2 * tid4;
            float2 cs = *reinterpret_cast<const float2*>(&sqb[c]);
            *reinterpret_cast<float2*>(&pd[r0 * PP + c]) =
                make_float2(2.f * acc[mf][nf][0] - cs.x, 2.f * acc[mf][nf][1] - cs.y);
            *reinterpret_cast<float2*>(&pd[r1 * PP + c]) =
                make_float2(2.f * acc[mf][nf][2] - cs.x, 2.f * acc[mf][nf][3] - cs.y);
        }
    }

    if (!diag) {
        float* st = (float*)dsm;
        #pragma unroll
        for (int mf = 0; mf < 2; mf++) {
            int rl0 = warp_m * 32 + mf * 16 + g;
            int rl1 = rl0 + 8;
            #pragma unroll
            for (int nf = 0; nf < 8; nf++) {
                int cl = warp_n * 64 + nf * 8 + 2 * tid4;
                st[rl0 * 129 + cl]     = 2.f * acc[mf][nf][0];
                st[rl0 * 129 + cl + 1] = 2.f * acc[mf][nf][1];
                st[rl1 * 129 + cl]     = 2.f * acc[mf][nf][2];
                st[rl1 * 129 + cl + 1] = 2.f * acc[mf][nf][3];
            }
        }
        __syncthreads();
        for (int i = tid; i < 128 * 32; i += 256) {
            int cl = i >> 5;
            int r  = (i & 31) * 4;
            float4 sv;
            sv.x = st[(r + 0) * 129 + cl];
            sv.y = st[(r + 1) * 129 + cl];
            sv.z = st[(r + 2) * 129 + cl];
            sv.w = st[(r + 3) * 129 + cl];
            float4 sq4 = *reinterpret_cast<const float4*>(&sqb[aRow + r]);
            float4 o = make_float4(sv.x - sq4.x, sv.y - sq4.y, sv.z - sq4.z, sv.w - sq4.w);
            *reinterpret_cast<float4*>(&pd[(bRow + cl) * PP + aRow + r]) = o;
        }
    }
}

// ---------------- top-20 per row: register-resident (strided loads) ----------------
__global__ void __launch_bounds__(256) topk_kernel(int rowbase) {
    int warp = threadIdx.x >> 5, lane = threadIdx.x & 31;
    int row = rowbase + blockIdx.x * 8 + warp;
    const float* __restrict__ prow = g_pd + (size_t)row * PP;

    float v[32];
    #pragma unroll
    for (int slot = 0; slot < 32; slot++) v[slot] = __ldg(&prow[slot * 32 + lane]);

    float m1 = -INFINITY, m2 = -INFINITY;
    int i1 = PP, i2 = PP;
    #pragma unroll
    for (int slot = 0; slot < 32; slot++) {
        float x = v[slot];
        int j = slot * 32 + lane;
        if (x > m1) { m2 = m1; i2 = i1; m1 = x; i1 = j; }
        else if (x > m2) { m2 = x; i2 = j; }
    }
    bool have2 = true;
    unsigned mask = 0;

    for (int k = 0; k < KNN; k++) {
        float best = m1; int bi = i1;
        #pragma unroll
        for (int o = 16; o; o >>= 1) {
            float ov = __shfl_xor_sync(0xffffffffu, best, o);
            int   oi = __shfl_xor_sync(0xffffffffu, bi, o);
            if (ov > best || (ov == best && oi < bi)) { best = ov; bi = oi; }
        }
        if (lane == 0) g_knn[row * KNN + k] = bi;
        if (i1 == bi) {
            mask |= 1u << (bi >> 5);
            if (have2) { m1 = m2; i1 = i2; have2 = false; }
            else {
                m1 = -INFINITY; m2 = -INFINITY; i1 = PP; i2 = PP;
                #pragma unroll
                for (int slot = 0; slot < 32; slot++) {
                    if (!(mask & (1u << slot))) {
                        float x = v[slot];
                        int j = slot * 32 + lane;
                        if (x > m1) { m2 = m1; i2 = i1; m1 = x; i1 = j; }
                        else if (x > m2) { m2 = x; i2 = j; }
                    }
                }
                have2 = true;
            }
        }
    }
}

// ---------------- aggregate + fused next-stage sq + bf16 split output ----------------
__global__ void __launch_bounds__(256) agg_kernel(
    const float* __restrict__ uw,
    const float* __restrict__ s, const float* __restrict__ bias,
    int O, int coloff, float* __restrict__ sqout, int bbase) {
    __shared__ int sidx[128];
    __shared__ float red[256];
    int tid = threadIdx.x;
    int G = 256 / O;
    int pi = tid / O;
    int o = tid - pi * O;
    int bl = blockIdx.y;
    int b = bbase + bl;
    int p = blockIdx.x * G + pi;
    size_t base = (size_t)b * PP + p;

    if (tid < G * KNN) {
        int gp = tid / KNN, kk = tid - gp * KNN;
        sidx[tid] = g_knn[((size_t)b * PP + blockIdx.x * G + gp) * KNN + kk];
    }
    __syncthreads();

    int twoO = 2 * O;
    const float* __restrict__ ub = uw + (size_t)bl * PP * twoO;
    float wv = __ldg(&ub[(size_t)p * twoO + O + o]);
    float sv = s[o], bv = bias[o];
    const int* idx = sidx + pi * KNN;
    float m = -INFINITY;
    #pragma unroll
    for (int k = 0; k < KNN; k++) {
        int nb = idx[k];
        float y = __ldg(&ub[(size_t)nb * twoO + o]) + wv;
        y = y * sv + bv;
        y = (y > 0.f) ? y : 0.2f * y;
        m = fmaxf(m, y);
    }
    bsplit(m, g_xch[base * 512 + coloff + o], g_xcl[base * 512 + coloff + o]);

    red[tid] = m * m;
    __syncthreads();
    for (int st = O >> 1; st > 0; st >>= 1) {
        if (o < st) red[tid] += red[tid + st];
        __syncthreads();
    }
    if (o == 0) sqout[base] = red[tid];
}

// ---------------- MLP head (pool combine + float4 dot products) ----------------
__global__ void head_kernel(const float* __restrict__ L1, const float* __restrict__ s6, const float* __restrict__ b6,
                            const float* __restrict__ L2, const float* __restrict__ bl2,
                            const float* __restrict__ s7, const float* __restrict__ b7,
                            const float* __restrict__ L3, const float* __restrict__ bl3,
                            float* __restrict__ out) {
    __shared__ __align__(16) float sf[1024];
    __shared__ __align__(16) float z1[512];
    __shared__ float z2[256];
    int b = blockIdx.x, t = threadIdx.x;
    {
        float mx = -INFINITY, sm = 0.f;
        #pragma unroll
        for (int c = 0; c < 8; c++) {
            mx = fmaxf(mx, g_pmax[(b * 8 + c) * 512 + t]);
            sm += g_psum[(b * 8 + c) * 512 + t];
        }
        sf[t] = mx;
        sf[t + 512] = sm * (1.0f / PP);
    }
    __syncthreads();
    {
        float a = 0.f;
        const float4* r = reinterpret_cast<const float4*>(L1 + (size_t)t * 1024);
        const float4* sf4 = reinterpret_cast<const float4*>(sf);
        for (int j = 0; j < 256; j++) {
            float4 rv = __ldg(&r[j]);
            float4 xv = sf4[j];
            a += xv.x * rv.x;
            a += xv.y * rv.y;
            a += xv.z * rv.z;
            a += xv.w * rv.w;
        }
        a = a * s6[t] + b6[t];
        z1[t] = (a > 0.f) ? a : 0.2f * a;
    }
    __syncthreads();
    if (t < 256) {
        float a = 0.f;
        const float4* r = reinterpret_cast<const float4*>(L2 + (size_t)t * 512);
        const float4* z14 = reinterpret_cast<const float4*>(z1);
        for (int j = 0; j < 128; j++) {
            float4 rv = __ldg(&r[j]);
            float4 xv = z14[j];
            a += xv.x * rv.x;
            a += xv.y * rv.y;
            a += xv.z * rv.z;
            a += xv.w * rv.w;
        }
        a = (a + bl2[t]) * s7[t] + b7[t];
        a = (a > 0.f) ? a : 0.2f * a;
        z2[t] = a * L3[t];
    }
    __syncthreads();
    if (t < 128) z2[t] += z2[t + 128];
    __syncthreads();
    if (t < 64) z2[t] += z2[t + 64];
    __syncthreads();
    if (t < 32) {
        float v = z2[t] + z2[t + 32];
        #pragma unroll
        for (int o = 16; o; o >>= 1) v += __shfl_down_sync(0xffffffffu, v, o);
        if (t == 0) {
            float z = v + bl3[0];
            out[b] = 1.0f / (1.0f + expf(-z));
        }
    }
}

// ---------------- host orchestration (R16 schedule) ----------------
extern "C" void kernel_launch(void* const* d_in, const int* in_sizes, int n_in,
                              void* d_out, int out_size) {
    const int* clusters;
    const float* features;
    if (in_sizes[0] == BB * PP) {
        clusters = (const int*)d_in[0];
        features = (const float*)d_in[1];
    } else {
        features = (const float*)d_in[0];
        clusters = (const int*)d_in[1];
    }
    const float* W1  = (const float*)d_in[2];
    const float* s1p = (const float*)d_in[3];
    const float* b1  = (const float*)d_in[4];
    const float* W2  = (const float*)d_in[5];
    const float* s2  = (const float*)d_in[6];
    const float* b2  = (const float*)d_in[7];
    const float* W3  = (const float*)d_in[8];
    const float* s3  = (const float*)d_in[9];
    const float* b3  = (const float*)d_in[10];
    const float* W4  = (const float*)d_in[11];
    const float* s4  = (const float*)d_in[12];
    const float* b4  = (const float*)d_in[13];
    const float* W5  = (const float*)d_in[14];
    const float* s5  = (const float*)d_in[15];
    const float* b5  = (const float*)d_in[16];
    const float* L1  = (const float*)d_in[17];
    const float* s6  = (const float*)d_in[18];
    const float* b6  = (const float*)d_in[19];
    const float* L2  = (const float*)d_in[20];
    const float* bl2 = (const float*)d_in[21];
    const float* s7  = (const float*)d_in[22];
    const float* b7  = (const float*)d_in[23];
    const float* L3  = (const float*)d_in[24];
    const float* bl3 = (const float*)d_in[25];
    float* out = (float*)d_out;

    static cudaStream_t s1s = nullptr;
    static cudaEvent_t evRoot, evA, evP, evG1;
    if (!s1s) {
        cudaFuncSetAttribute(mmagemm<EPI_PLAIN>, cudaFuncAttributeMaxDynamicSharedMemorySize, GEMM_SMEM);
        cudaFuncSetAttribute(mmagemm<EPI_POOL>,  cudaFuncAttributeMaxDynamicSharedMemorySize, GEMM_SMEM);
        cudaFuncSetAttribute(pdsym,              cudaFuncAttributeMaxDynamicSharedMemorySize, GEMM_SMEM);
        cudaStreamCreateWithFlags(&s1s, cudaStreamNonBlocking);
        cudaEventCreateWithFlags(&evRoot, cudaEventDisableTiming);
        cudaEventCreateWithFlags(&evA, cudaEventDisableTiming);
        cudaEventCreateWithFlags(&evP, cudaEventDisableTiming);
        cudaEventCreateWithFlags(&evG1, cudaEventDisableTiming);
    }

    float *uw, *sq, *pmax, *psum;
    __nv_bfloat16 *h0h, *h0l, *xch, *xcl;
    __nv_bfloat16 *w1h, *w1l, *w2h, *w2l, *w3h, *w3l, *w4h, *w4l, *w5h, *w5l;
    cudaGetSymbolAddress((void**)&uw, g_uw);
    cudaGetSymbolAddress((void**)&sq, g_sq);
    cudaGetSymbolAddress((void**)&pmax, g_pmax);
    cudaGetSymbolAddress((void**)&psum, g_psum);
    cudaGetSymbolAddress((void**)&h0h, g_h0h);
    cudaGetSymbolAddress((void**)&h0l, g_h0l);
    cudaGetSymbolAddress((void**)&xch, g_xch);
    cudaGetSymbolAddress((void**)&xcl, g_xcl);
    cudaGetSymbolAddress((void**)&w1h, g_w1h); cudaGetSymbolAddress((void**)&w1l, g_w1l);
    cudaGetSymbolAddress((void**)&w2h, g_w2h); cudaGetSymbolAddress((void**)&w2l, g_w2l);
    cudaGetSymbolAddress((void**)&w3h, g_w3h); cudaGetSymbolAddress((void**)&w3l, g_w3l);
    cudaGetSymbolAddress((void**)&w4h, g_w4h); cudaGetSymbolAddress((void**)&w4l, g_w4l);
    cudaGetSymbolAddress((void**)&w5h, g_w5h); cudaGetSymbolAddress((void**)&w5l, g_w5l);

    const __nv_bfloat16* hh[4] = { h0h, xch, xch, xch };
    const __nv_bfloat16* hl[4] = { h0l, xcl, xcl, xcl };
    int lda_s[4]   = { 128, 512, 512, 512 };
    int coff_s[4]  = { 0, 0, 64, 128 };
    int C_s[4]     = { 128, 64, 64, 128 };
    int O_s[4]     = { 64, 64, 128, 256 };
    const __nv_bfloat16* wh_s[4] = { w1h, w2h, w3h, w4h };
    const __nv_bfloat16* wl_s[4] = { w1l, w2l, w3l, w4l };
    const float* ss_s[4] = { s1p, s2, s3, s4 };
    const float* bb_s[4] = { b1, b2, b3, b4 };
    int ocoff_s[4] = { 0, 64, 128, 256 };

    // fork: prep on side stream
    cudaEventRecord(evRoot, 0);
    cudaStreamWaitEvent(s1s, evRoot, 0);
    prep_kernel<<<(8192 + 4096 + 8192 + 32768 + 262144 + 255) / 256, 256, 0, s1s>>>(W1, W2, W3, W4, W5);
    cudaEventRecord(evP, s1s);

    // gather + fused sq (warp per point)
    gather_kernel<<<BB * PP / 8, 256>>>(features, clusters);
    cudaEventRecord(evA, 0);

    cudaStreamWaitEvent(0, evP, 0);
    cudaStreamWaitEvent(s1s, evA, 0);

    cudaStream_t streams[2] = { 0, s1s };
    for (int grp = 0; grp < 2; grp++) {
        cudaStream_t st = streams[grp];
        int bbase = grp * GB;
        float* uwg = uw + (size_t)grp * GB * PP * 512;

        for (int s = 0; s < 4; s++) {
            long strideA = (long)PP * lda_s[s];
            int C = C_s[s], O = O_s[s];
            size_t hoff = (size_t)bbase * PP * lda_s[s];

            mmagemm<EPI_PLAIN><<<dim3((2 * O) / 128, (GB * PP) / 128, 1), 256, GEMM_SMEM, st>>>(
                hh[s] + hoff, hl[s] + hoff, lda_s[s], 0, coff_s[s],
                wh_s[s], wl_s[s], C, 0, 0,
                uwg, 2 * O, 0,
                C, nullptr, nullptr, nullptr, nullptr);

            pdsym<<<dim3(36, 1, GB), 256, GEMM_SMEM, st>>>(
                hh[s], hl[s], lda_s[s], strideA, coff_s[s], C, bbase);

            topk_kernel<<<GB * PP / 8, 256, 0, st>>>(bbase * PP);

            int Gp = 256 / O;
            agg_kernel<<<dim3(PP / Gp, GB), 256, 0, st>>>(
                uwg, ss_s[s], bb_s[s], O, ocoff_s[s], sq, bbase);
        }

        mmagemm<EPI_POOL><<<dim3(4, (GB * PP) / 128, 1), 256, GEMM_SMEM, st>>>(
            xch + (size_t)bbase * PP * 512, xcl + (size_t)bbase * PP * 512, 512, 0, 0,
            w5h, w5l, 512, 0, 0,
            nullptr, 0, 0,
            512, s5, b5, pmax + (size_t)bbase * 8 * 512, psum + (size_t)bbase * 8 * 512);
    }

    cudaEventRecord(evG1, s1s);
    cudaStreamWaitEvent(0, evG1, 0);
    head_kernel<<<BB, 512>>>(L1, s6, b6, L2, bl2, s7, b7, L3, bl3, out);
}